// round 1
// baseline (speedup 1.0000x reference)
#include <cuda_runtime.h>
#include <cuda_bf16.h>

// ---------------------------------------------------------------------------
// GNN_37082747634058: 3-layer GraphSAGE(mean) forward.
// Strategy:
//   per layer: histogram(dst) -> exclusive scan -> scatter src ids (CSR) ->
//              warp-per-dst mean aggregation -> fused GEMM
//              out = relu?( [mean | x_dst] @ [Wl;Wr] + bl )
// GEMM uses fma.rn.f32x2 (FFMA2) for 2x fp32 rate on sm_103a.
// ---------------------------------------------------------------------------

#define N0 1363968
#define N1 123904
#define N2 11264
#define N3 1024
#define E0 1239040
#define E1 112640
#define E2 10240
#define D_IN 128
#define D_H  256
#define D_OUT 64

// ------------------------- static device scratch ---------------------------
__device__ float g_mean0[(size_t)N1 * D_IN];
__device__ float g_h0   [(size_t)N1 * D_H];
__device__ float g_mean1[(size_t)N2 * D_H];
__device__ float g_h1   [(size_t)N2 * D_H];
__device__ float g_mean2[(size_t)N3 * D_H];

__device__ int g_cnt0[N1], g_off0[N1 + 1], g_cur0[N1], g_esrc0[E0];
__device__ int g_cnt1[N2], g_off1[N2 + 1], g_cur1[N2], g_esrc1[E1];
__device__ int g_cnt2[N3], g_off2[N3 + 1], g_cur2[N3], g_esrc2[E2];

// ------------------------------ helpers ------------------------------------
__device__ __forceinline__ void ffma2(unsigned long long& c, unsigned long long a,
                                      unsigned long long b) {
    asm("fma.rn.f32x2 %0, %1, %2, %0;" : "+l"(c) : "l"(a), "l"(b));
}
__device__ __forceinline__ unsigned long long pack2(float x) {
    unsigned long long r;
    asm("mov.b64 %0, {%1, %1};" : "=l"(r) : "f"(x));
    return r;
}
__device__ __forceinline__ float2 unpack2(unsigned long long c) {
    float2 f;
    asm("mov.b64 {%0, %1}, %2;" : "=f"(f.x), "=f"(f.y) : "l"(c));
    return f;
}

// ------------------------------ CSR build ----------------------------------
__global__ void zero_kernel(int* __restrict__ p, int n) {
    int i = blockIdx.x * blockDim.x + threadIdx.x;
    if (i < n) p[i] = 0;
}

__global__ void hist_kernel(const int* __restrict__ dst, int e, int* __restrict__ cnt) {
    int i = blockIdx.x * blockDim.x + threadIdx.x;
    if (i < e) atomicAdd(&cnt[dst[i]], 1);
}

// single-block exclusive scan (1024 threads x 4 elems per iter)
__global__ void exscan_kernel(const int* __restrict__ cnt, int n,
                              int* __restrict__ off, int* __restrict__ cur) {
    __shared__ int wsum[32];
    __shared__ int tot_sh;
    __shared__ int carry_sh;
    const int t = threadIdx.x;
    const int lane = t & 31;
    const int w = t >> 5;
    if (t == 0) carry_sh = 0;
    __syncthreads();
    const int CH = 4096;
    for (int base = 0; base < n; base += CH) {
        int idx = base + t * 4;
        int v[4];
#pragma unroll
        for (int i = 0; i < 4; i++) v[i] = (idx + i < n) ? cnt[idx + i] : 0;
        int s = v[0] + v[1] + v[2] + v[3];
        int incl = s;
#pragma unroll
        for (int d = 1; d < 32; d <<= 1) {
            int o = __shfl_up_sync(0xffffffffu, incl, d);
            if (lane >= d) incl += o;
        }
        if (lane == 31) wsum[w] = incl;
        __syncthreads();
        if (w == 0) {
            int x = wsum[lane];
            int xi = x;
#pragma unroll
            for (int d = 1; d < 32; d <<= 1) {
                int o = __shfl_up_sync(0xffffffffu, xi, d);
                if (lane >= d) xi += o;
            }
            if (lane == 31) tot_sh = xi;
            wsum[lane] = xi - x;  // exclusive
        }
        __syncthreads();
        int carry = carry_sh;
        int run = carry + wsum[w] + (incl - s);
#pragma unroll
        for (int i = 0; i < 4; i++) {
            if (idx + i < n) { off[idx + i] = run; cur[idx + i] = run; }
            run += v[i];
        }
        __syncthreads();
        if (t == 0) carry_sh += tot_sh;
    }
    if (t == 0) off[n] = carry_sh;
}

__global__ void scatter_kernel(const int* __restrict__ src, const int* __restrict__ dst,
                               int e, int* __restrict__ cur, int* __restrict__ out_src) {
    int i = blockIdx.x * blockDim.x + threadIdx.x;
    if (i < e) {
        int p = atomicAdd(&cur[dst[i]], 1);
        out_src[p] = src[i];
    }
}

// ------------------------- warp-per-dst mean aggregation -------------------
template <int D>  // 128 or 256
__global__ void aggregate_kernel(const float* __restrict__ X,
                                 const int* __restrict__ off,
                                 const int* __restrict__ srcs,
                                 float* __restrict__ out, int n_dst) {
    int g = (blockIdx.x * blockDim.x + threadIdx.x) >> 5;
    if (g >= n_dst) return;
    int lane = threadIdx.x & 31;
    int beg = off[g], end = off[g + 1];
    float4 a0 = make_float4(0.f, 0.f, 0.f, 0.f);
    float4 a1 = make_float4(0.f, 0.f, 0.f, 0.f);
    for (int j = beg; j < end; j++) {
        int s = srcs[j];
        const float4* row = (const float4*)(X + (size_t)s * D);
        float4 v = row[lane];
        a0.x += v.x; a0.y += v.y; a0.z += v.z; a0.w += v.w;
        if (D == 256) {
            float4 u = row[lane + 32];
            a1.x += u.x; a1.y += u.y; a1.z += u.z; a1.w += u.w;
        }
    }
    int c = end - beg;
    float inv = 1.0f / (float)(c > 0 ? c : 1);
    float4* o = (float4*)(out + (size_t)g * D);
    o[lane] = make_float4(a0.x * inv, a0.y * inv, a0.z * inv, a0.w * inv);
    if (D == 256)
        o[lane + 32] = make_float4(a1.x * inv, a1.y * inv, a1.z * inv, a1.w * inv);
}

// ----------------------------- fused SAGE GEMM -----------------------------
// C[M,N] = relu?( [Aagg(K1) | Adst(K2)] @ [Wl;Wr] + bias )
// Exact tiling assumed: M%BM==0, N%BN==0, K1%BK==0, K2%BK==0.
template <int BM, int BN, int BK, int TM, int TN, bool RELU>
__global__ void __launch_bounds__((BM / TM) * (BN / TN))
sage_gemm_kernel(const float* __restrict__ Aagg, int K1,
                 const float* __restrict__ Adst, int K2, int ldDst,
                 const float* __restrict__ Wl, const float* __restrict__ Wr,
                 const float* __restrict__ bias,
                 float* __restrict__ C, int N) {
    constexpr int THREADS = (BM / TM) * (BN / TN);
    constexpr int LDA = BM + 4;
    __shared__ float As[BK][LDA];
    __shared__ float Bs[BK][BN];

    const int tid = threadIdx.x;
    const int tx = tid % (BN / TN);
    const int ty = tid / (BN / TN);
    const int rowBase = blockIdx.y * BM;
    const int colBase = blockIdx.x * BN;
    const int K = K1 + K2;

    unsigned long long c2[TM / 2][TN];
#pragma unroll
    for (int i = 0; i < TM / 2; i++)
#pragma unroll
        for (int j = 0; j < TN; j++) c2[i][j] = 0ull;

    constexpr int ACOLS4 = BK / 4;
    const int acol4 = tid % ACOLS4;
    const int arow = tid / ACOLS4;
    constexpr int AROWS_PER = THREADS / ACOLS4;
    constexpr int APASS = BM / AROWS_PER;

    constexpr int BCOLS4 = BN / 4;
    const int bcol4 = tid % BCOLS4;
    const int brow = tid / BCOLS4;
    constexpr int BROWS_PER = THREADS / BCOLS4;
    constexpr int BPASS = BK / BROWS_PER;

    for (int k0 = 0; k0 < K; k0 += BK) {
        const bool inAgg = (k0 < K1);
#pragma unroll
        for (int p = 0; p < APASS; p++) {
            int r = arow + p * AROWS_PER;
            int grow = rowBase + r;
            const float* src = inAgg
                ? (Aagg + (size_t)grow * K1 + k0 + acol4 * 4)
                : (Adst + (size_t)grow * ldDst + (k0 - K1) + acol4 * 4);
            float4 v = *(const float4*)src;
            As[acol4 * 4 + 0][r] = v.x;
            As[acol4 * 4 + 1][r] = v.y;
            As[acol4 * 4 + 2][r] = v.z;
            As[acol4 * 4 + 3][r] = v.w;
        }
#pragma unroll
        for (int p = 0; p < BPASS; p++) {
            int r = brow + p * BROWS_PER;
            int kg = k0 + r;
            const float* src = (kg < K1)
                ? (Wl + (size_t)kg * N + colBase + bcol4 * 4)
                : (Wr + (size_t)(kg - K1) * N + colBase + bcol4 * 4);
            *(float4*)&Bs[r][bcol4 * 4] = *(const float4*)src;
        }
        __syncthreads();
#pragma unroll
        for (int kk = 0; kk < BK; kk++) {
            unsigned long long a2[TM / 2];
#pragma unroll
            for (int i = 0; i < TM / 2; i++)
                a2[i] = *(const unsigned long long*)&As[kk][ty * TM + 2 * i];
            unsigned long long bb[TN];
#pragma unroll
            for (int j = 0; j < TN; j++) bb[j] = pack2(Bs[kk][tx * TN + j]);
#pragma unroll
            for (int i = 0; i < TM / 2; i++)
#pragma unroll
                for (int j = 0; j < TN; j++) ffma2(c2[i][j], a2[i], bb[j]);
        }
        __syncthreads();
    }
#pragma unroll
    for (int j = 0; j < TN; j++) {
        int n = colBase + tx * TN + j;
        float bj = bias[n];
#pragma unroll
        for (int i = 0; i < TM / 2; i++) {
            float2 v = unpack2(c2[i][j]);
            float lo = v.x + bj;
            float hi = v.y + bj;
            if (RELU) { lo = fmaxf(lo, 0.f); hi = fmaxf(hi, 0.f); }
            int m = rowBase + ty * TM + 2 * i;
            C[(size_t)m * N + n] = lo;
            C[(size_t)(m + 1) * N + n] = hi;
        }
    }
}

// ------------------------------- launcher ----------------------------------
static inline int cdiv(int a, int b) { return (a + b - 1) / b; }

extern "C" void kernel_launch(void* const* d_in, const int* in_sizes, int n_in,
                              void* d_out, int out_size) {
    const float* x   = (const float*)d_in[0];
    const float* Wl0 = (const float*)d_in[1];
    const float* bl0 = (const float*)d_in[2];
    const float* Wr0 = (const float*)d_in[3];
    const float* Wl1 = (const float*)d_in[4];
    const float* bl1 = (const float*)d_in[5];
    const float* Wr1 = (const float*)d_in[6];
    const float* Wl2 = (const float*)d_in[7];
    const float* bl2 = (const float*)d_in[8];
    const float* Wr2 = (const float*)d_in[9];
    const int* es0 = (const int*)d_in[10];
    const int* ed0 = (const int*)d_in[11];
    const int* es1 = (const int*)d_in[12];
    const int* ed1 = (const int*)d_in[13];
    const int* es2 = (const int*)d_in[14];
    const int* ed2 = (const int*)d_in[15];
    float* out = (float*)d_out;

    float *mean0, *h0, *mean1, *h1, *mean2;
    int *cnt0, *off0, *cur0, *esrc0;
    int *cnt1, *off1, *cur1, *esrc1;
    int *cnt2, *off2, *cur2, *esrc2;
    cudaGetSymbolAddress((void**)&mean0, g_mean0);
    cudaGetSymbolAddress((void**)&h0, g_h0);
    cudaGetSymbolAddress((void**)&mean1, g_mean1);
    cudaGetSymbolAddress((void**)&h1, g_h1);
    cudaGetSymbolAddress((void**)&mean2, g_mean2);
    cudaGetSymbolAddress((void**)&cnt0, g_cnt0);
    cudaGetSymbolAddress((void**)&off0, g_off0);
    cudaGetSymbolAddress((void**)&cur0, g_cur0);
    cudaGetSymbolAddress((void**)&esrc0, g_esrc0);
    cudaGetSymbolAddress((void**)&cnt1, g_cnt1);
    cudaGetSymbolAddress((void**)&off1, g_off1);
    cudaGetSymbolAddress((void**)&cur1, g_cur1);
    cudaGetSymbolAddress((void**)&esrc1, g_esrc1);
    cudaGetSymbolAddress((void**)&cnt2, g_cnt2);
    cudaGetSymbolAddress((void**)&off2, g_off2);
    cudaGetSymbolAddress((void**)&cur2, g_cur2);
    cudaGetSymbolAddress((void**)&esrc2, g_esrc2);

    // ---------------- layer 0 ----------------
    zero_kernel<<<cdiv(N1, 256), 256>>>(cnt0, N1);
    hist_kernel<<<cdiv(E0, 256), 256>>>(ed0, E0, cnt0);
    exscan_kernel<<<1, 1024>>>(cnt0, N1, off0, cur0);
    scatter_kernel<<<cdiv(E0, 256), 256>>>(es0, ed0, E0, cur0, esrc0);
    aggregate_kernel<128><<<cdiv(N1 * 32, 256), 256>>>(x, off0, esrc0, mean0, N1);
    sage_gemm_kernel<128, 128, 16, 8, 8, true>
        <<<dim3(D_H / 128, N1 / 128), 256>>>(mean0, D_IN, x, D_IN, D_IN,
                                             Wl0, Wr0, bl0, h0, D_H);

    // ---------------- layer 1 ----------------
    zero_kernel<<<cdiv(N2, 256), 256>>>(cnt1, N2);
    hist_kernel<<<cdiv(E1, 256), 256>>>(ed1, E1, cnt1);
    exscan_kernel<<<1, 1024>>>(cnt1, N2, off1, cur1);
    scatter_kernel<<<cdiv(E1, 256), 256>>>(es1, ed1, E1, cur1, esrc1);
    aggregate_kernel<256><<<cdiv(N2 * 32, 256), 256>>>(h0, off1, esrc1, mean1, N2);
    sage_gemm_kernel<128, 128, 16, 8, 8, false>
        <<<dim3(D_H / 128, N2 / 128), 256>>>(mean1, D_H, h0, D_H, D_H,
                                             Wl1, Wr1, bl1, h1, D_H);

    // ---------------- layer 2 ----------------
    zero_kernel<<<cdiv(N3, 256), 256>>>(cnt2, N3);
    hist_kernel<<<cdiv(E2, 256), 256>>>(ed2, E2, cnt2);
    exscan_kernel<<<1, 1024>>>(cnt2, N3, off2, cur2);
    scatter_kernel<<<cdiv(E2, 256), 256>>>(es2, ed2, E2, cur2, esrc2);
    aggregate_kernel<256><<<cdiv(N3 * 32, 256), 256>>>(h1, off2, esrc2, mean2, N3);
    sage_gemm_kernel<64, 64, 16, 4, 4, true>
        <<<dim3(D_OUT / 64, N3 / 64), 256>>>(mean2, D_H, h1, D_H, D_H,
                                             Wl2, Wr2, bl2, out, D_OUT);
}

// round 3
// speedup vs baseline: 1.3347x; 1.3347x over previous
#include <cuda_runtime.h>
#include <cuda_bf16.h>
#include <cstdint>

// ---------------------------------------------------------------------------
// GNN_37082747634058: 3-layer GraphSAGE(mean) forward.
//   per layer: histogram -> scan -> scatter (CSR) -> warp-per-dst mean ->
//              GEMM  out = relu?( [mean | x_dst] @ [Wl;Wr] + bl )
// Layers 0,1 GEMM: mma.sync tf32 (tensor pipe), 3xTF32 split for fp32 accuracy.
// Layer 2 GEMM: FFMA2 (tiny).
// NOTE: tcgen05 PTX is rejected by this harness's virtual target (compute_103,
// no 'a' suffix) -- mma.sync is the arch-generic tensor path.
// ---------------------------------------------------------------------------

#define N0 1363968
#define N1 123904
#define N2 11264
#define N3 1024
#define E0 1239040
#define E1 112640
#define E2 10240
#define D_IN 128
#define D_H  256
#define D_OUT 64

// ------------------------- static device scratch ---------------------------
__device__ float g_mean0[(size_t)N1 * D_IN];
__device__ float g_h0   [(size_t)N1 * D_H];
__device__ float g_mean1[(size_t)N2 * D_H];
__device__ float g_h1   [(size_t)N2 * D_H];
__device__ float g_mean2[(size_t)N3 * D_H];

__device__ float g_wt0_hi[256 * 256], g_wt0_lo[256 * 256];
__device__ float g_wt1_hi[256 * 512], g_wt1_lo[256 * 512];

__device__ int g_cnt0[N1], g_off0[N1 + 1], g_cur0[N1], g_esrc0[E0];
__device__ int g_cnt1[N2], g_off1[N2 + 1], g_cur1[N2], g_esrc1[E1];
__device__ int g_cnt2[N3], g_off2[N3 + 1], g_cur2[N3], g_esrc2[E2];

// ------------------------------ helpers ------------------------------------
__device__ __forceinline__ float tf32_rna(float x) {
    uint32_t u;
    asm("cvt.rna.tf32.f32 %0, %1;" : "=r"(u) : "f"(x));
    return __uint_as_float(u);
}

__device__ __forceinline__ void mma_tf32(float (&c)[4], const float (&a)[4],
                                         const float (&b)[2]) {
    asm volatile(
        "mma.sync.aligned.m16n8k8.row.col.f32.tf32.tf32.f32 "
        "{%0,%1,%2,%3}, {%4,%5,%6,%7}, {%8,%9}, {%0,%1,%2,%3};"
        : "+f"(c[0]), "+f"(c[1]), "+f"(c[2]), "+f"(c[3])
        : "r"(__float_as_uint(a[0])), "r"(__float_as_uint(a[1])),
          "r"(__float_as_uint(a[2])), "r"(__float_as_uint(a[3])),
          "r"(__float_as_uint(b[0])), "r"(__float_as_uint(b[1])));
}

// FFMA2 helpers (layer-2 small GEMM)
__device__ __forceinline__ void ffma2(unsigned long long& c, unsigned long long a,
                                      unsigned long long b) {
    asm("fma.rn.f32x2 %0, %1, %2, %0;" : "+l"(c) : "l"(a), "l"(b));
}
__device__ __forceinline__ unsigned long long pack2(float x) {
    unsigned long long r;
    asm("mov.b64 %0, {%1, %1};" : "=l"(r) : "f"(x));
    return r;
}
__device__ __forceinline__ float2 unpack2(unsigned long long c) {
    float2 f;
    asm("mov.b64 {%0, %1}, %2;" : "=f"(f.x), "=f"(f.y) : "l"(c));
    return f;
}

// ------------------------------ CSR build ----------------------------------
__global__ void zero_kernel(int* __restrict__ p, int n) {
    int i = blockIdx.x * blockDim.x + threadIdx.x;
    if (i < n) p[i] = 0;
}
__global__ void hist_kernel(const int* __restrict__ dst, int e, int* __restrict__ cnt) {
    int i = blockIdx.x * blockDim.x + threadIdx.x;
    if (i < e) atomicAdd(&cnt[dst[i]], 1);
}
__global__ void exscan_kernel(const int* __restrict__ cnt, int n,
                              int* __restrict__ off, int* __restrict__ cur) {
    __shared__ int wsum[32];
    __shared__ int tot_sh;
    __shared__ int carry_sh;
    const int t = threadIdx.x;
    const int lane = t & 31;
    const int w = t >> 5;
    if (t == 0) carry_sh = 0;
    __syncthreads();
    const int CH = 4096;
    for (int base = 0; base < n; base += CH) {
        int idx = base + t * 4;
        int v[4];
#pragma unroll
        for (int i = 0; i < 4; i++) v[i] = (idx + i < n) ? cnt[idx + i] : 0;
        int s = v[0] + v[1] + v[2] + v[3];
        int incl = s;
#pragma unroll
        for (int d = 1; d < 32; d <<= 1) {
            int o = __shfl_up_sync(0xffffffffu, incl, d);
            if (lane >= d) incl += o;
        }
        if (lane == 31) wsum[w] = incl;
        __syncthreads();
        if (w == 0) {
            int x = wsum[lane];
            int xi = x;
#pragma unroll
            for (int d = 1; d < 32; d <<= 1) {
                int o = __shfl_up_sync(0xffffffffu, xi, d);
                if (lane >= d) xi += o;
            }
            if (lane == 31) tot_sh = xi;
            wsum[lane] = xi - x;
        }
        __syncthreads();
        int carry = carry_sh;
        int run = carry + wsum[w] + (incl - s);
#pragma unroll
        for (int i = 0; i < 4; i++) {
            if (idx + i < n) { off[idx + i] = run; cur[idx + i] = run; }
            run += v[i];
        }
        __syncthreads();
        if (t == 0) carry_sh += tot_sh;
    }
    if (t == 0) off[n] = carry_sh;
}
__global__ void scatter_kernel(const int* __restrict__ src, const int* __restrict__ dst,
                               int e, int* __restrict__ cur, int* __restrict__ out_src) {
    int i = blockIdx.x * blockDim.x + threadIdx.x;
    if (i < e) {
        int p = atomicAdd(&cur[dst[i]], 1);
        out_src[p] = src[i];
    }
}

// ------------------------- warp-per-dst mean aggregation -------------------
template <int D>
__global__ void aggregate_kernel(const float* __restrict__ X,
                                 const int* __restrict__ off,
                                 const int* __restrict__ srcs,
                                 float* __restrict__ out, int n_dst) {
    int g = (blockIdx.x * blockDim.x + threadIdx.x) >> 5;
    if (g >= n_dst) return;
    int lane = threadIdx.x & 31;
    int beg = off[g], end = off[g + 1];
    float4 a0 = make_float4(0.f, 0.f, 0.f, 0.f);
    float4 a1 = make_float4(0.f, 0.f, 0.f, 0.f);
    for (int j = beg; j < end; j++) {
        int s = srcs[j];
        const float4* row = (const float4*)(X + (size_t)s * D);
        float4 v = row[lane];
        a0.x += v.x; a0.y += v.y; a0.z += v.z; a0.w += v.w;
        if (D == 256) {
            float4 u = row[lane + 32];
            a1.x += u.x; a1.y += u.y; a1.z += u.z; a1.w += u.w;
        }
    }
    int c = end - beg;
    float inv = 1.0f / (float)(c > 0 ? c : 1);
    float4* o = (float4*)(out + (size_t)g * D);
    o[lane] = make_float4(a0.x * inv, a0.y * inv, a0.z * inv, a0.w * inv);
    if (D == 256)
        o[lane + 32] = make_float4(a1.x * inv, a1.y * inv, a1.z * inv, a1.w * inv);
}

// ------------------- weight transpose + tf32 hi/lo split -------------------
// Wcat[K][N] (rows 0..K1-1 = Wl, K1..K-1 = Wr) -> Wt_hi/Wt_lo [N][K] K-major.
__global__ void prep_w_kernel(const float* __restrict__ Wl, const float* __restrict__ Wr,
                              int K1, int K, int N,
                              float* __restrict__ hi, float* __restrict__ lo) {
    int idx = blockIdx.x * blockDim.x + threadIdx.x;
    if (idx >= N * K) return;
    int n = idx / K, k = idx % K;
    float v = (k < K1) ? Wl[(size_t)k * N + n] : Wr[(size_t)(k - K1) * N + n];
    float h = tf32_rna(v);
    hi[(size_t)n * K + k] = h;
    lo[(size_t)n * K + k] = tf32_rna(v - h);
}

// ------------------------- mma.sync tf32 SAGE GEMM -------------------------
// C[M,N] = relu?( [Aagg(K1 cols) | Adst] @ Wt^T + bias ), 3xTF32 split.
// CTA tile 128x128, 8 warps (4m x 2n), warp tile 32x64, K chunked by 32.
// SMEM arrays use stride 36 floats: fragment reads hit all 32 banks.
template <int N, bool RELU>
__global__ void __launch_bounds__(256)
sage_mma_gemm(const float* __restrict__ Aagg, int K1,
              const float* __restrict__ Adst, int ldDst, int K,
              const float* __restrict__ Wt_hi, const float* __restrict__ Wt_lo,
              const float* __restrict__ bias, float* __restrict__ C) {
    extern __shared__ float sm[];
    constexpr int STR = 36;
    float* Ah = sm;
    float* Al = Ah + 128 * STR;
    float* Bh = Al + 128 * STR;
    float* Bl = Bh + 128 * STR;

    const int tid = threadIdx.x;
    const int wid = tid >> 5;
    const int lane = tid & 31;
    const int g = lane >> 2;   // group id (0..7)
    const int t = lane & 3;    // thread in group
    const int wm = (wid & 3) * 32;
    const int wn = (wid >> 2) * 64;
    const int rowBase = blockIdx.y * 128;
    const int colBase = blockIdx.x * 128;
    const int NC = K / 32;

    float acc[2][8][4];
#pragma unroll
    for (int im = 0; im < 2; im++)
#pragma unroll
        for (int in_ = 0; in_ < 8; in_++)
#pragma unroll
            for (int q = 0; q < 4; q++) acc[im][in_][q] = 0.f;

    for (int kc = 0; kc < NC; kc++) {
        const int acol = kc * 32;
        // ---- load A chunk (128 rows x 32 k), split hi/lo ----
        {
            const bool inAgg = acol < K1;
            const float* abase = inAgg ? (Aagg + acol) : (Adst + (acol - K1));
            const int ald = inAgg ? K1 : ldDst;
#pragma unroll
            for (int p = 0; p < 4; p++) {
                int idx = p * 256 + tid;
                int r = idx >> 3, c4 = idx & 7;
                float4 v = *(const float4*)(abase + (size_t)(rowBase + r) * ald + c4 * 4);
                float4 h, l;
                h.x = tf32_rna(v.x); l.x = tf32_rna(v.x - h.x);
                h.y = tf32_rna(v.y); l.y = tf32_rna(v.y - h.y);
                h.z = tf32_rna(v.z); l.z = tf32_rna(v.z - h.z);
                h.w = tf32_rna(v.w); l.w = tf32_rna(v.w - h.w);
                *(float4*)&Ah[r * STR + c4 * 4] = h;
                *(float4*)&Al[r * STR + c4 * 4] = l;
            }
            // ---- load B chunk (128 n-rows x 32 k) ----
#pragma unroll
            for (int p = 0; p < 4; p++) {
                int idx = p * 256 + tid;
                int r = idx >> 3, c4 = idx & 7;
                const size_t gidx = (size_t)(colBase + r) * K + acol + c4 * 4;
                *(float4*)&Bh[r * STR + c4 * 4] = *(const float4*)(Wt_hi + gidx);
                *(float4*)&Bl[r * STR + c4 * 4] = *(const float4*)(Wt_lo + gidx);
            }
        }
        __syncthreads();
#pragma unroll
        for (int kk = 0; kk < 4; kk++) {
            const int c = kk * 8 + t;
            float ah[2][4], al[2][4];
#pragma unroll
            for (int im = 0; im < 2; im++) {
                int r = wm + im * 16 + g;
                ah[im][0] = Ah[r * STR + c];
                ah[im][1] = Ah[(r + 8) * STR + c];
                ah[im][2] = Ah[r * STR + c + 4];
                ah[im][3] = Ah[(r + 8) * STR + c + 4];
                al[im][0] = Al[r * STR + c];
                al[im][1] = Al[(r + 8) * STR + c];
                al[im][2] = Al[r * STR + c + 4];
                al[im][3] = Al[(r + 8) * STR + c + 4];
            }
#pragma unroll
            for (int in_ = 0; in_ < 8; in_++) {
                int n = wn + in_ * 8 + g;
                float bh[2] = {Bh[n * STR + c], Bh[n * STR + c + 4]};
                float bl[2] = {Bl[n * STR + c], Bl[n * STR + c + 4]};
                mma_tf32(acc[0][in_], ah[0], bh);
                mma_tf32(acc[1][in_], ah[1], bh);
                mma_tf32(acc[0][in_], ah[0], bl);
                mma_tf32(acc[1][in_], ah[1], bl);
                mma_tf32(acc[0][in_], al[0], bh);
                mma_tf32(acc[1][in_], al[1], bh);
            }
        }
        __syncthreads();
    }

    // ---- epilogue ----
#pragma unroll
    for (int in_ = 0; in_ < 8; in_++) {
        const int col = colBase + wn + in_ * 8 + 2 * t;
        const float b0 = __ldg(bias + col);
        const float b1 = __ldg(bias + col + 1);
#pragma unroll
        for (int im = 0; im < 2; im++) {
            const int row = rowBase + wm + im * 16 + g;
            float v0 = acc[im][in_][0] + b0;
            float v1 = acc[im][in_][1] + b1;
            float v2 = acc[im][in_][2] + b0;
            float v3 = acc[im][in_][3] + b1;
            if (RELU) {
                v0 = fmaxf(v0, 0.f); v1 = fmaxf(v1, 0.f);
                v2 = fmaxf(v2, 0.f); v3 = fmaxf(v3, 0.f);
            }
            *(float2*)&C[(size_t)row * N + col] = make_float2(v0, v1);
            *(float2*)&C[(size_t)(row + 8) * N + col] = make_float2(v2, v3);
        }
    }
}

// ----------------------- FFMA2 GEMM (layer 2 only) -------------------------
template <int BM, int BN, int BK, int TM, int TN, bool RELU>
__global__ void __launch_bounds__((BM / TM) * (BN / TN))
sage_gemm_kernel(const float* __restrict__ Aagg, int K1,
                 const float* __restrict__ Adst, int K2, int ldDst,
                 const float* __restrict__ Wl, const float* __restrict__ Wr,
                 const float* __restrict__ bias,
                 float* __restrict__ C, int N) {
    constexpr int THREADS = (BM / TM) * (BN / TN);
    constexpr int LDA = BM + 4;
    __shared__ float As[BK][LDA];
    __shared__ float Bs[BK][BN];

    const int tid = threadIdx.x;
    const int tx = tid % (BN / TN);
    const int ty = tid / (BN / TN);
    const int rowBase = blockIdx.y * BM;
    const int colBase = blockIdx.x * BN;
    const int K = K1 + K2;

    unsigned long long c2[TM / 2][TN];
#pragma unroll
    for (int i = 0; i < TM / 2; i++)
#pragma unroll
        for (int j = 0; j < TN; j++) c2[i][j] = 0ull;

    constexpr int ACOLS4 = BK / 4;
    const int acol4 = tid % ACOLS4;
    const int arow = tid / ACOLS4;
    constexpr int AROWS_PER = THREADS / ACOLS4;
    constexpr int APASS = BM / AROWS_PER;

    constexpr int BCOLS4 = BN / 4;
    const int bcol4 = tid % BCOLS4;
    const int brow = tid / BCOLS4;
    constexpr int BROWS_PER = THREADS / BCOLS4;
    constexpr int BPASS = BK / BROWS_PER;

    for (int k0 = 0; k0 < K; k0 += BK) {
        const bool inAgg = (k0 < K1);
#pragma unroll
        for (int p = 0; p < APASS; p++) {
            int r = arow + p * AROWS_PER;
            int grow = rowBase + r;
            const float* src = inAgg
                ? (Aagg + (size_t)grow * K1 + k0 + acol4 * 4)
                : (Adst + (size_t)grow * ldDst + (k0 - K1) + acol4 * 4);
            float4 v = *(const float4*)src;
            As[acol4 * 4 + 0][r] = v.x;
            As[acol4 * 4 + 1][r] = v.y;
            As[acol4 * 4 + 2][r] = v.z;
            As[acol4 * 4 + 3][r] = v.w;
        }
#pragma unroll
        for (int p = 0; p < BPASS; p++) {
            int r = brow + p * BROWS_PER;
            int kg = k0 + r;
            const float* src = (kg < K1)
                ? (Wl + (size_t)kg * N + colBase + bcol4 * 4)
                : (Wr + (size_t)(kg - K1) * N + colBase + bcol4 * 4);
            *(float4*)&Bs[r][bcol4 * 4] = *(const float4*)src;
        }
        __syncthreads();
#pragma unroll
        for (int kk = 0; kk < BK; kk++) {
            unsigned long long a2[TM / 2];
#pragma unroll
            for (int i = 0; i < TM / 2; i++)
                a2[i] = *(const unsigned long long*)&As[kk][ty * TM + 2 * i];
            unsigned long long bb[TN];
#pragma unroll
            for (int j = 0; j < TN; j++) bb[j] = pack2(Bs[kk][tx * TN + j]);
#pragma unroll
            for (int i = 0; i < TM / 2; i++)
#pragma unroll
                for (int j = 0; j < TN; j++) ffma2(c2[i][j], a2[i], bb[j]);
        }
        __syncthreads();
    }
#pragma unroll
    for (int j = 0; j < TN; j++) {
        int n = colBase + tx * TN + j;
        float bj = bias[n];
#pragma unroll
        for (int i = 0; i < TM / 2; i++) {
            float2 v = unpack2(c2[i][j]);
            float lo = v.x + bj;
            float hi = v.y + bj;
            if (RELU) { lo = fmaxf(lo, 0.f); hi = fmaxf(hi, 0.f); }
            int m = rowBase + ty * TM + 2 * i;
            C[(size_t)m * N + n] = lo;
            C[(size_t)(m + 1) * N + n] = hi;
        }
    }
}

// ------------------------------- launcher ----------------------------------
static inline int cdiv(int a, int b) { return (a + b - 1) / b; }

extern "C" void kernel_launch(void* const* d_in, const int* in_sizes, int n_in,
                              void* d_out, int out_size) {
    const float* x   = (const float*)d_in[0];
    const float* Wl0 = (const float*)d_in[1];
    const float* bl0 = (const float*)d_in[2];
    const float* Wr0 = (const float*)d_in[3];
    const float* Wl1 = (const float*)d_in[4];
    const float* bl1 = (const float*)d_in[5];
    const float* Wr1 = (const float*)d_in[6];
    const float* Wl2 = (const float*)d_in[7];
    const float* bl2 = (const float*)d_in[8];
    const float* Wr2 = (const float*)d_in[9];
    const int* es0 = (const int*)d_in[10];
    const int* ed0 = (const int*)d_in[11];
    const int* es1 = (const int*)d_in[12];
    const int* ed1 = (const int*)d_in[13];
    const int* es2 = (const int*)d_in[14];
    const int* ed2 = (const int*)d_in[15];
    float* out = (float*)d_out;

    float *mean0, *h0, *mean1, *h1, *mean2;
    float *wt0h, *wt0l, *wt1h, *wt1l;
    int *cnt0, *off0, *cur0, *esrc0;
    int *cnt1, *off1, *cur1, *esrc1;
    int *cnt2, *off2, *cur2, *esrc2;
    cudaGetSymbolAddress((void**)&mean0, g_mean0);
    cudaGetSymbolAddress((void**)&h0, g_h0);
    cudaGetSymbolAddress((void**)&mean1, g_mean1);
    cudaGetSymbolAddress((void**)&h1, g_h1);
    cudaGetSymbolAddress((void**)&mean2, g_mean2);
    cudaGetSymbolAddress((void**)&wt0h, g_wt0_hi);
    cudaGetSymbolAddress((void**)&wt0l, g_wt0_lo);
    cudaGetSymbolAddress((void**)&wt1h, g_wt1_hi);
    cudaGetSymbolAddress((void**)&wt1l, g_wt1_lo);
    cudaGetSymbolAddress((void**)&cnt0, g_cnt0);
    cudaGetSymbolAddress((void**)&off0, g_off0);
    cudaGetSymbolAddress((void**)&cur0, g_cur0);
    cudaGetSymbolAddress((void**)&esrc0, g_esrc0);
    cudaGetSymbolAddress((void**)&cnt1, g_cnt1);
    cudaGetSymbolAddress((void**)&off1, g_off1);
    cudaGetSymbolAddress((void**)&cur1, g_cur1);
    cudaGetSymbolAddress((void**)&esrc1, g_esrc1);
    cudaGetSymbolAddress((void**)&cnt2, g_cnt2);
    cudaGetSymbolAddress((void**)&off2, g_off2);
    cudaGetSymbolAddress((void**)&cur2, g_cur2);
    cudaGetSymbolAddress((void**)&esrc2, g_esrc2);

    constexpr int SMEM_MMA = 4 * 128 * 36 * 4;  // 73728 bytes
    cudaFuncSetAttribute(sage_mma_gemm<256, true>,
                         cudaFuncAttributeMaxDynamicSharedMemorySize, SMEM_MMA);
    cudaFuncSetAttribute(sage_mma_gemm<256, false>,
                         cudaFuncAttributeMaxDynamicSharedMemorySize, SMEM_MMA);

    // weight prep (independent of graph work)
    prep_w_kernel<<<cdiv(256 * 256, 256), 256>>>(Wl0, Wr0, D_IN, 2 * D_IN, D_H, wt0h, wt0l);
    prep_w_kernel<<<cdiv(256 * 512, 256), 256>>>(Wl1, Wr1, D_H, 2 * D_H, D_H, wt1h, wt1l);

    // ---------------- layer 0 ----------------
    zero_kernel<<<cdiv(N1, 256), 256>>>(cnt0, N1);
    hist_kernel<<<cdiv(E0, 256), 256>>>(ed0, E0, cnt0);
    exscan_kernel<<<1, 1024>>>(cnt0, N1, off0, cur0);
    scatter_kernel<<<cdiv(E0, 256), 256>>>(es0, ed0, E0, cur0, esrc0);
    aggregate_kernel<128><<<cdiv(N1 * 32, 256), 256>>>(x, off0, esrc0, mean0, N1);
    sage_mma_gemm<256, true><<<dim3(2, N1 / 128), 256, SMEM_MMA>>>(
        mean0, D_IN, x, D_IN, 2 * D_IN, wt0h, wt0l, bl0, h0);

    // ---------------- layer 1 ----------------
    zero_kernel<<<cdiv(N2, 256), 256>>>(cnt1, N2);
    hist_kernel<<<cdiv(E1, 256), 256>>>(ed1, E1, cnt1);
    exscan_kernel<<<1, 1024>>>(cnt1, N2, off1, cur1);
    scatter_kernel<<<cdiv(E1, 256), 256>>>(es1, ed1, E1, cur1, esrc1);
    aggregate_kernel<256><<<cdiv(N2 * 32, 256), 256>>>(h0, off1, esrc1, mean1, N2);
    sage_mma_gemm<256, false><<<dim3(2, N2 / 128), 256, SMEM_MMA>>>(
        mean1, D_H, h0, D_H, 2 * D_H, wt1h, wt1l, bl1, h1);

    // ---------------- layer 2 ----------------
    zero_kernel<<<cdiv(N3, 256), 256>>>(cnt2, N3);
    hist_kernel<<<cdiv(E2, 256), 256>>>(ed2, E2, cnt2);
    exscan_kernel<<<1, 1024>>>(cnt2, N3, off2, cur2);
    scatter_kernel<<<cdiv(E2, 256), 256>>>(es2, ed2, E2, cur2, esrc2);
    aggregate_kernel<256><<<cdiv(N3 * 32, 256), 256>>>(h1, off2, esrc2, mean2, N3);
    sage_gemm_kernel<64, 64, 16, 4, 4, true>
        <<<dim3(D_OUT / 64, N3 / 64), 256>>>(mean2, D_H, h1, D_H, D_H,
                                             Wl2, Wr2, bl2, out, D_OUT);
}

// round 4
// speedup vs baseline: 1.4722x; 1.1030x over previous
#include <cuda_runtime.h>
#include <cuda_bf16.h>
#include <cstdint>

// ---------------------------------------------------------------------------
// GNN_37082747634058: 3-layer GraphSAGE(mean) forward.
//   CSR build (fused across layers) -> per layer: warp-per-dst mean ->
//   GEMM out = relu?( [mean | x_dst] @ [Wl;Wr] + bl )
// Layers 0,1 GEMM: mma.sync tf32 (3xTF32 split, fp32 accuracy), cp.async
// double-buffered, 128x256 CTA tile, raw operands split in registers.
// Layer 2 GEMM: FFMA2 (tiny).
// ---------------------------------------------------------------------------

#define N0 1363968
#define N1 123904
#define N2 11264
#define N3 1024
#define E0 1239040
#define E1 112640
#define E2 10240
#define D_IN 128
#define D_H  256
#define D_OUT 64

// ------------------------- static device scratch ---------------------------
__device__ float g_mean0[(size_t)N1 * D_IN];
__device__ float g_h0   [(size_t)N1 * D_H];
__device__ float g_mean1[(size_t)N2 * D_H];
__device__ float g_h1   [(size_t)N2 * D_H];
__device__ float g_mean2[(size_t)N3 * D_H];

__device__ float g_wt0[256 * 256];   // Wt0[n][k], k = 0..255 (Wl0;Wr0)
__device__ float g_wt1[256 * 512];   // Wt1[n][k], k = 0..511 (Wl1;Wr1)

__device__ int g_cnt0[N1], g_off0[N1 + 1], g_cur0[N1], g_esrc0[E0];
__device__ int g_cnt1[N2], g_off1[N2 + 1], g_cur1[N2], g_esrc1[E1];
__device__ int g_cnt2[N3], g_off2[N3 + 1], g_cur2[N3], g_esrc2[E2];

// ------------------------------ helpers ------------------------------------
__device__ __forceinline__ float tf32_rna(float x) {
    uint32_t u;
    asm("cvt.rna.tf32.f32 %0, %1;" : "=r"(u) : "f"(x));
    return __uint_as_float(u);
}

__device__ __forceinline__ void mma_tf32(float (&c)[4], const float (&a)[4],
                                         const float (&b)[2]) {
    asm volatile(
        "mma.sync.aligned.m16n8k8.row.col.f32.tf32.tf32.f32 "
        "{%0,%1,%2,%3}, {%4,%5,%6,%7}, {%8,%9}, {%0,%1,%2,%3};"
        : "+f"(c[0]), "+f"(c[1]), "+f"(c[2]), "+f"(c[3])
        : "r"(__float_as_uint(a[0])), "r"(__float_as_uint(a[1])),
          "r"(__float_as_uint(a[2])), "r"(__float_as_uint(a[3])),
          "r"(__float_as_uint(b[0])), "r"(__float_as_uint(b[1])));
}

__device__ __forceinline__ void cp_async16(void* smem_dst, const void* gmem_src) {
    uint32_t s = (uint32_t)__cvta_generic_to_shared(smem_dst);
    asm volatile("cp.async.cg.shared.global [%0], [%1], 16;\n"
                 :: "r"(s), "l"(gmem_src));
}
__device__ __forceinline__ void cp_async_commit() {
    asm volatile("cp.async.commit_group;\n" ::: "memory");
}
template <int NWait>
__device__ __forceinline__ void cp_async_wait() {
    asm volatile("cp.async.wait_group %0;\n" :: "n"(NWait) : "memory");
}

// FFMA2 helpers (layer-2 small GEMM)
__device__ __forceinline__ void ffma2(unsigned long long& c, unsigned long long a,
                                      unsigned long long b) {
    asm("fma.rn.f32x2 %0, %1, %2, %0;" : "+l"(c) : "l"(a), "l"(b));
}
__device__ __forceinline__ unsigned long long pack2(float x) {
    unsigned long long r;
    asm("mov.b64 %0, {%1, %1};" : "=l"(r) : "f"(x));
    return r;
}
__device__ __forceinline__ float2 unpack2(unsigned long long c) {
    float2 f;
    asm("mov.b64 {%0, %1}, %2;" : "=f"(f.x), "=f"(f.y) : "l"(c));
    return f;
}

// --------------------------- fused CSR build -------------------------------
__global__ void zero_all_kernel(int* c0, int* c1, int* c2) {
    int i = blockIdx.x * blockDim.x + threadIdx.x;
    if (i < N1) c0[i] = 0;
    else if (i < N1 + N2) c1[i - N1] = 0;
    else if (i < N1 + N2 + N3) c2[i - N1 - N2] = 0;
}

__global__ void hist_all_kernel(const int* d0, const int* d1, const int* d2,
                                int* c0, int* c1, int* c2) {
    int i = blockIdx.x * blockDim.x + threadIdx.x;
    if (i < E0) atomicAdd(&c0[d0[i]], 1);
    else if (i < E0 + E1) atomicAdd(&c1[d1[i - E0]], 1);
    else if (i < E0 + E1 + E2) atomicAdd(&c2[d2[i - E0 - E1]], 1);
}

__device__ void exscan_block(const int* __restrict__ cnt, int n,
                             int* __restrict__ off, int* __restrict__ cur) {
    __shared__ int wsum[32];
    __shared__ int tot_sh;
    __shared__ int carry_sh;
    const int t = threadIdx.x;
    const int lane = t & 31;
    const int w = t >> 5;
    if (t == 0) carry_sh = 0;
    __syncthreads();
    const int CH = 4096;
    for (int base = 0; base < n; base += CH) {
        int idx = base + t * 4;
        int v[4];
#pragma unroll
        for (int i = 0; i < 4; i++) v[i] = (idx + i < n) ? cnt[idx + i] : 0;
        int s = v[0] + v[1] + v[2] + v[3];
        int incl = s;
#pragma unroll
        for (int d = 1; d < 32; d <<= 1) {
            int o = __shfl_up_sync(0xffffffffu, incl, d);
            if (lane >= d) incl += o;
        }
        if (lane == 31) wsum[w] = incl;
        __syncthreads();
        if (w == 0) {
            int x = wsum[lane];
            int xi = x;
#pragma unroll
            for (int d = 1; d < 32; d <<= 1) {
                int o = __shfl_up_sync(0xffffffffu, xi, d);
                if (lane >= d) xi += o;
            }
            if (lane == 31) tot_sh = xi;
            wsum[lane] = xi - x;
        }
        __syncthreads();
        int carry = carry_sh;
        int run = carry + wsum[w] + (incl - s);
#pragma unroll
        for (int i = 0; i < 4; i++) {
            if (idx + i < n) { off[idx + i] = run; cur[idx + i] = run; }
            run += v[i];
        }
        __syncthreads();
        if (t == 0) carry_sh += tot_sh;
    }
    if (t == 0) off[n] = carry_sh;
}

__global__ void exscan3_kernel(const int* c0, int* o0, int* u0,
                               const int* c1, int* o1, int* u1,
                               const int* c2, int* o2, int* u2) {
    if (blockIdx.x == 0) exscan_block(c0, N1, o0, u0);
    else if (blockIdx.x == 1) exscan_block(c1, N2, o1, u1);
    else exscan_block(c2, N3, o2, u2);
}

__global__ void scatter_all_kernel(const int* s0, const int* d0, int* u0, int* e0,
                                   const int* s1, const int* d1, int* u1, int* e1,
                                   const int* s2, const int* d2, int* u2, int* e2) {
    int i = blockIdx.x * blockDim.x + threadIdx.x;
    if (i < E0) {
        int p = atomicAdd(&u0[d0[i]], 1); e0[p] = s0[i];
    } else if (i < E0 + E1) {
        int j = i - E0;
        int p = atomicAdd(&u1[d1[j]], 1); e1[p] = s1[j];
    } else if (i < E0 + E1 + E2) {
        int j = i - E0 - E1;
        int p = atomicAdd(&u2[d2[j]], 1); e2[p] = s2[j];
    }
}

// ------------------------- warp-per-dst mean aggregation -------------------
template <int D>
__global__ void aggregate_kernel(const float* __restrict__ X,
                                 const int* __restrict__ off,
                                 const int* __restrict__ srcs,
                                 float* __restrict__ out, int n_dst) {
    int g = (blockIdx.x * blockDim.x + threadIdx.x) >> 5;
    if (g >= n_dst) return;
    int lane = threadIdx.x & 31;
    int beg = off[g], end = off[g + 1];
    float4 a0 = make_float4(0.f, 0.f, 0.f, 0.f);
    float4 a1 = make_float4(0.f, 0.f, 0.f, 0.f);
    int j = beg;
    for (; j + 1 < end; j += 2) {
        int s0 = srcs[j], s1 = srcs[j + 1];
        const float4* r0 = (const float4*)(X + (size_t)s0 * D);
        const float4* r1 = (const float4*)(X + (size_t)s1 * D);
        float4 v0 = r0[lane];
        float4 v1 = r1[lane];
        a0.x += v0.x + v1.x; a0.y += v0.y + v1.y;
        a0.z += v0.z + v1.z; a0.w += v0.w + v1.w;
        if (D == 256) {
            float4 u0 = r0[lane + 32];
            float4 u1 = r1[lane + 32];
            a1.x += u0.x + u1.x; a1.y += u0.y + u1.y;
            a1.z += u0.z + u1.z; a1.w += u0.w + u1.w;
        }
    }
    if (j < end) {
        int s = srcs[j];
        const float4* row = (const float4*)(X + (size_t)s * D);
        float4 v = row[lane];
        a0.x += v.x; a0.y += v.y; a0.z += v.z; a0.w += v.w;
        if (D == 256) {
            float4 u = row[lane + 32];
            a1.x += u.x; a1.y += u.y; a1.z += u.z; a1.w += u.w;
        }
    }
    int c = end - beg;
    float inv = 1.0f / (float)(c > 0 ? c : 1);
    float4* o = (float4*)(out + (size_t)g * D);
    o[lane] = make_float4(a0.x * inv, a0.y * inv, a0.z * inv, a0.w * inv);
    if (D == 256)
        o[lane + 32] = make_float4(a1.x * inv, a1.y * inv, a1.z * inv, a1.w * inv);
}

// ------------------------ weight transpose (raw) ---------------------------
// Wcat[K][N] (rows 0..K1-1 = Wl, K1..K-1 = Wr) -> Wt [N][K] K-major, raw fp32.
__global__ void prep_w_kernel(const float* __restrict__ Wl, const float* __restrict__ Wr,
                              int K1, int K, int N, float* __restrict__ wt) {
    int idx = blockIdx.x * blockDim.x + threadIdx.x;
    if (idx >= N * K) return;
    int n = idx / K, k = idx % K;
    wt[(size_t)n * K + k] =
        (k < K1) ? Wl[(size_t)k * N + n] : Wr[(size_t)(k - K1) * N + n];
}

// ------------------------- mma.sync tf32 SAGE GEMM -------------------------
// C[M,N] = relu?( [Aagg(K1 cols) | Adst] @ Wt^T + bias ), 3xTF32 split.
// CTA tile 128 x N(=256), 8 warps (4m x 2n), warp tile 32x128.
// Raw fp32 staged via cp.async (double buffered); hi/lo split in registers.
template <int N, bool RELU>
__global__ void __launch_bounds__(256, 1)
sage_mma_gemm(const float* __restrict__ Aagg, int K1,
              const float* __restrict__ Adst, int ldDst, int K,
              const float* __restrict__ Wt,
              const float* __restrict__ bias, float* __restrict__ C) {
    extern __shared__ float sm[];
    constexpr int STR = 36;
    constexpr int ABUF = 128 * STR;      // floats per A buffer
    constexpr int BBUF = N * STR;        // floats per B buffer
    float* As[2] = {sm, sm + ABUF + BBUF};
    float* Bs[2] = {sm + ABUF, sm + ABUF + BBUF + ABUF};

    const int tid = threadIdx.x;
    const int wid = tid >> 5;
    const int lane = tid & 31;
    const int g = lane >> 2;
    const int t = lane & 3;
    const int wm = (wid & 3) * 32;
    const int wn = (wid >> 2) * (N / 2);
    const int rowBase = blockIdx.x * 128;
    const int NC = K / 32;
    constexpr int NIN = N / 16;          // in_ iterations per warp (8 cols each)

    float acc[2][NIN][4];
#pragma unroll
    for (int im = 0; im < 2; im++)
#pragma unroll
        for (int i = 0; i < NIN; i++)
#pragma unroll
            for (int q = 0; q < 4; q++) acc[im][i][q] = 0.f;

    auto issue_chunk = [&](int kc, int b) {
        const int acol = kc * 32;
        const bool inAgg = acol < K1;
        const float* abase = inAgg ? (Aagg + acol) : (Adst + (acol - K1));
        const int ald = inAgg ? K1 : ldDst;
#pragma unroll
        for (int p = 0; p < 4; p++) {
            int idx = p * 256 + tid;
            int r = idx >> 3, c4 = idx & 7;
            cp_async16(&As[b][r * STR + c4 * 4],
                       abase + (size_t)(rowBase + r) * ald + c4 * 4);
        }
#pragma unroll
        for (int p = 0; p < N / 32; p++) {
            int idx = p * 256 + tid;
            int r = idx >> 3, c4 = idx & 7;
            cp_async16(&Bs[b][r * STR + c4 * 4],
                       Wt + (size_t)r * K + acol + c4 * 4);
        }
        cp_async_commit();
    };

    issue_chunk(0, 0);

    for (int kc = 0; kc < NC; kc++) {
        const int b = kc & 1;
        const bool more = (kc + 1 < NC);
        if (more) issue_chunk(kc + 1, b ^ 1);
        if (more) cp_async_wait<1>(); else cp_async_wait<0>();
        __syncthreads();

        const float* Ab = As[b];
        const float* Bb = Bs[b];
#pragma unroll
        for (int kk = 0; kk < 4; kk++) {
            const int c = kk * 8 + t;
            float ah[2][4], al[2][4];
#pragma unroll
            for (int im = 0; im < 2; im++) {
                const int r = wm + im * 16 + g;
                float v0 = Ab[r * STR + c];
                float v1 = Ab[(r + 8) * STR + c];
                float v2 = Ab[r * STR + c + 4];
                float v3 = Ab[(r + 8) * STR + c + 4];
                ah[im][0] = tf32_rna(v0); al[im][0] = tf32_rna(v0 - ah[im][0]);
                ah[im][1] = tf32_rna(v1); al[im][1] = tf32_rna(v1 - ah[im][1]);
                ah[im][2] = tf32_rna(v2); al[im][2] = tf32_rna(v2 - ah[im][2]);
                ah[im][3] = tf32_rna(v3); al[im][3] = tf32_rna(v3 - ah[im][3]);
            }
#pragma unroll
            for (int i = 0; i < NIN; i++) {
                const int n = wn + i * 8 + g;
                float b0 = Bb[n * STR + c];
                float b1 = Bb[n * STR + c + 4];
                float bh[2], bl[2];
                bh[0] = tf32_rna(b0); bl[0] = tf32_rna(b0 - bh[0]);
                bh[1] = tf32_rna(b1); bl[1] = tf32_rna(b1 - bh[1]);
                mma_tf32(acc[0][i], ah[0], bh);
                mma_tf32(acc[1][i], ah[1], bh);
                mma_tf32(acc[0][i], ah[0], bl);
                mma_tf32(acc[1][i], ah[1], bl);
                mma_tf32(acc[0][i], al[0], bh);
                mma_tf32(acc[1][i], al[1], bh);
            }
        }
        __syncthreads();
    }

    // ---- epilogue ----
#pragma unroll
    for (int i = 0; i < NIN; i++) {
        const int col = wn + i * 8 + 2 * t;
        const float b0 = __ldg(bias + col);
        const float b1 = __ldg(bias + col + 1);
#pragma unroll
        for (int im = 0; im < 2; im++) {
            const int row = rowBase + wm + im * 16 + g;
            float v0 = acc[im][i][0] + b0;
            float v1 = acc[im][i][1] + b1;
            float v2 = acc[im][i][2] + b0;
            float v3 = acc[im][i][3] + b1;
            if (RELU) {
                v0 = fmaxf(v0, 0.f); v1 = fmaxf(v1, 0.f);
                v2 = fmaxf(v2, 0.f); v3 = fmaxf(v3, 0.f);
            }
            *(float2*)&C[(size_t)row * N + col] = make_float2(v0, v1);
            *(float2*)&C[(size_t)(row + 8) * N + col] = make_float2(v2, v3);
        }
    }
}

// ----------------------- FFMA2 GEMM (layer 2 only) -------------------------
template <int BM, int BN, int BK, int TM, int TN, bool RELU>
__global__ void __launch_bounds__((BM / TM) * (BN / TN))
sage_gemm_kernel(const float* __restrict__ Aagg, int K1,
                 const float* __restrict__ Adst, int K2, int ldDst,
                 const float* __restrict__ Wl, const float* __restrict__ Wr,
                 const float* __restrict__ bias,
                 float* __restrict__ C, int N) {
    constexpr int THREADS = (BM / TM) * (BN / TN);
    constexpr int LDA = BM + 4;
    __shared__ float As[BK][LDA];
    __shared__ float Bs[BK][BN];

    const int tid = threadIdx.x;
    const int tx = tid % (BN / TN);
    const int ty = tid / (BN / TN);
    const int rowBase = blockIdx.y * BM;
    const int colBase = blockIdx.x * BN;
    const int K = K1 + K2;

    unsigned long long c2[TM / 2][TN];
#pragma unroll
    for (int i = 0; i < TM / 2; i++)
#pragma unroll
        for (int j = 0; j < TN; j++) c2[i][j] = 0ull;

    constexpr int ACOLS4 = BK / 4;
    const int acol4 = tid % ACOLS4;
    const int arow = tid / ACOLS4;
    constexpr int AROWS_PER = THREADS / ACOLS4;
    constexpr int APASS = BM / AROWS_PER;

    constexpr int BCOLS4 = BN / 4;
    const int bcol4 = tid % BCOLS4;
    const int brow = tid / BCOLS4;
    constexpr int BROWS_PER = THREADS / BCOLS4;
    constexpr int BPASS = BK / BROWS_PER;

    for (int k0 = 0; k0 < K; k0 += BK) {
        const bool inAgg = (k0 < K1);
#pragma unroll
        for (int p = 0; p < APASS; p++) {
            int r = arow + p * AROWS_PER;
            int grow = rowBase + r;
            const float* src = inAgg
                ? (Aagg + (size_t)grow * K1 + k0 + acol4 * 4)
                : (Adst + (size_t)grow * ldDst + (k0 - K1) + acol4 * 4);
            float4 v = *(const float4*)src;
            As[acol4 * 4 + 0][r] = v.x;
            As[acol4 * 4 + 1][r] = v.y;
            As[acol4 * 4 + 2][r] = v.z;
            As[acol4 * 4 + 3][r] = v.w;
        }
#pragma unroll
        for (int p = 0; p < BPASS; p++) {
            int r = brow + p * BROWS_PER;
            int kg = k0 + r;
            const float* src = (kg < K1)
                ? (Wl + (size_t)kg * N + colBase + bcol4 * 4)
                : (Wr + (size_t)(kg - K1) * N + colBase + bcol4 * 4);
            *(float4*)&Bs[r][bcol4 * 4] = *(const float4*)src;
        }
        __syncthreads();
#pragma unroll
        for (int kk = 0; kk < BK; kk++) {
            unsigned long long a2[TM / 2];
#pragma unroll
            for (int i = 0; i < TM / 2; i++)
                a2[i] = *(const unsigned long long*)&As[kk][ty * TM + 2 * i];
            unsigned long long bb[TN];
#pragma unroll
            for (int j = 0; j < TN; j++) bb[j] = pack2(Bs[kk][tx * TN + j]);
#pragma unroll
            for (int i = 0; i < TM / 2; i++)
#pragma unroll
                for (int j = 0; j < TN; j++) ffma2(c2[i][j], a2[i], bb[j]);
        }
        __syncthreads();
    }
#pragma unroll
    for (int j = 0; j < TN; j++) {
        int n = colBase + tx * TN + j;
        float bj = bias[n];
#pragma unroll
        for (int i = 0; i < TM / 2; i++) {
            float2 v = unpack2(c2[i][j]);
            float lo = v.x + bj;
            float hi = v.y + bj;
            if (RELU) { lo = fmaxf(lo, 0.f); hi = fmaxf(hi, 0.f); }
            int m = rowBase + ty * TM + 2 * i;
            C[(size_t)m * N + n] = lo;
            C[(size_t)(m + 1) * N + n] = hi;
        }
    }
}

// ------------------------------- launcher ----------------------------------
static inline int cdiv(int a, int b) { return (a + b - 1) / b; }

extern "C" void kernel_launch(void* const* d_in, const int* in_sizes, int n_in,
                              void* d_out, int out_size) {
    const float* x   = (const float*)d_in[0];
    const float* Wl0 = (const float*)d_in[1];
    const float* bl0 = (const float*)d_in[2];
    const float* Wr0 = (const float*)d_in[3];
    const float* Wl1 = (const float*)d_in[4];
    const float* bl1 = (const float*)d_in[5];
    const float* Wr1 = (const float*)d_in[6];
    const float* Wl2 = (const float*)d_in[7];
    const float* bl2 = (const float*)d_in[8];
    const float* Wr2 = (const float*)d_in[9];
    const int* es0 = (const int*)d_in[10];
    const int* ed0 = (const int*)d_in[11];
    const int* es1 = (const int*)d_in[12];
    const int* ed1 = (const int*)d_in[13];
    const int* es2 = (const int*)d_in[14];
    const int* ed2 = (const int*)d_in[15];
    float* out = (float*)d_out;

    float *mean0, *h0, *mean1, *h1, *mean2, *wt0, *wt1;
    int *cnt0, *off0, *cur0, *esrc0;
    int *cnt1, *off1, *cur1, *esrc1;
    int *cnt2, *off2, *cur2, *esrc2;
    cudaGetSymbolAddress((void**)&mean0, g_mean0);
    cudaGetSymbolAddress((void**)&h0, g_h0);
    cudaGetSymbolAddress((void**)&mean1, g_mean1);
    cudaGetSymbolAddress((void**)&h1, g_h1);
    cudaGetSymbolAddress((void**)&mean2, g_mean2);
    cudaGetSymbolAddress((void**)&wt0, g_wt0);
    cudaGetSymbolAddress((void**)&wt1, g_wt1);
    cudaGetSymbolAddress((void**)&cnt0, g_cnt0);
    cudaGetSymbolAddress((void**)&off0, g_off0);
    cudaGetSymbolAddress((void**)&cur0, g_cur0);
    cudaGetSymbolAddress((void**)&esrc0, g_esrc0);
    cudaGetSymbolAddress((void**)&cnt1, g_cnt1);
    cudaGetSymbolAddress((void**)&off1, g_off1);
    cudaGetSymbolAddress((void**)&cur1, g_cur1);
    cudaGetSymbolAddress((void**)&esrc1, g_esrc1);
    cudaGetSymbolAddress((void**)&cnt2, g_cnt2);
    cudaGetSymbolAddress((void**)&off2, g_off2);
    cudaGetSymbolAddress((void**)&cur2, g_cur2);
    cudaGetSymbolAddress((void**)&esrc2, g_esrc2);

    constexpr int SMEM_MMA = 2 * (128 * 36 + 256 * 36) * 4;  // 110592 bytes
    cudaFuncSetAttribute(sage_mma_gemm<256, true>,
                         cudaFuncAttributeMaxDynamicSharedMemorySize, SMEM_MMA);
    cudaFuncSetAttribute(sage_mma_gemm<256, false>,
                         cudaFuncAttributeMaxDynamicSharedMemorySize, SMEM_MMA);

    // weight transpose (independent of graph work)
    prep_w_kernel<<<cdiv(256 * 256, 256), 256>>>(Wl0, Wr0, D_IN, 2 * D_IN, D_H, wt0);
    prep_w_kernel<<<cdiv(256 * 512, 256), 256>>>(Wl1, Wr1, D_H, 2 * D_H, D_H, wt1);

    // fused CSR build for all three layers
    zero_all_kernel<<<cdiv(N1 + N2 + N3, 256), 256>>>(cnt0, cnt1, cnt2);
    hist_all_kernel<<<cdiv(E0 + E1 + E2, 256), 256>>>(ed0, ed1, ed2, cnt0, cnt1, cnt2);
    exscan3_kernel<<<3, 1024>>>(cnt0, off0, cur0, cnt1, off1, cur1, cnt2, off2, cur2);
    scatter_all_kernel<<<cdiv(E0 + E1 + E2, 256), 256>>>(
        es0, ed0, cur0, esrc0, es1, ed1, cur1, esrc1, es2, ed2, cur2, esrc2);

    // ---------------- layer 0 ----------------
    aggregate_kernel<128><<<cdiv(N1 * 32, 256), 256>>>(x, off0, esrc0, mean0, N1);
    sage_mma_gemm<256, true><<<N1 / 128, 256, SMEM_MMA>>>(
        mean0, D_IN, x, D_IN, 2 * D_IN, wt0, bl0, h0);

    // ---------------- layer 1 ----------------
    aggregate_kernel<256><<<cdiv(N2 * 32, 256), 256>>>(h0, off1, esrc1, mean1, N2);
    sage_mma_gemm<256, false><<<N2 / 128, 256, SMEM_MMA>>>(
        mean1, D_H, h0, D_H, 2 * D_H, wt1, bl1, h1);

    // ---------------- layer 2 ----------------
    aggregate_kernel<256><<<cdiv(N3 * 32, 256), 256>>>(h1, off2, esrc2, mean2, N3);
    sage_gemm_kernel<64, 64, 16, 4, 4, true>
        <<<dim3(D_OUT / 64, N3 / 64), 256>>>(mean2, D_H, h1, D_H, D_H,
                                             Wl2, Wr2, bl2, out, D_OUT);
}

// round 5
// speedup vs baseline: 1.8849x; 1.2804x over previous
#include <cuda_runtime.h>
#include <cuda_bf16.h>
#include <cstdint>

// ---------------------------------------------------------------------------
// GNN_37082747634058: 3-layer GraphSAGE(mean) forward.
//   fused CSR build -> per layer: warp-per-dst mean ->
//   GEMM out = relu?( [mean | x_dst] @ [Wl;Wr] + bl )
// Layers 0,1 GEMM: mma.sync m16n8k16 bf16 with 3-term split (hi*hi + hi*lo +
// lo*hi, fp32 accum) -- half the MMA instructions of tf32x3 at same accuracy
// class. Weights pre-split to bf16 hi/lo. cp.async double buffered.
// Layer 2 GEMM: FFMA2 (tiny).
// ---------------------------------------------------------------------------

#define N0 1363968
#define N1 123904
#define N2 11264
#define N3 1024
#define E0 1239040
#define E1 112640
#define E2 10240
#define D_IN 128
#define D_H  256
#define D_OUT 64

// ------------------------- static device scratch ---------------------------
__device__ float g_mean0[(size_t)N1 * D_IN];
__device__ float g_h0   [(size_t)N1 * D_H];
__device__ float g_mean1[(size_t)N2 * D_H];
__device__ float g_h1   [(size_t)N2 * D_H];
__device__ float g_mean2[(size_t)N3 * D_H];

__device__ __nv_bfloat16 g_wt0h[256 * 256], g_wt0l[256 * 256];
__device__ __nv_bfloat16 g_wt1h[256 * 512], g_wt1l[256 * 512];

__device__ int g_cnt0[N1], g_off0[N1 + 1], g_cur0[N1], g_esrc0[E0];
__device__ int g_cnt1[N2], g_off1[N2 + 1], g_cur1[N2], g_esrc1[E1];
__device__ int g_cnt2[N3], g_off2[N3 + 1], g_cur2[N3], g_esrc2[E2];

// ------------------------------ helpers ------------------------------------
__device__ __forceinline__ void mma_bf16(float (&c)[4], const uint32_t (&a)[4],
                                         const uint32_t (&b)[2]) {
    asm volatile(
        "mma.sync.aligned.m16n8k16.row.col.f32.bf16.bf16.f32 "
        "{%0,%1,%2,%3}, {%4,%5,%6,%7}, {%8,%9}, {%0,%1,%2,%3};"
        : "+f"(c[0]), "+f"(c[1]), "+f"(c[2]), "+f"(c[3])
        : "r"(a[0]), "r"(a[1]), "r"(a[2]), "r"(a[3]), "r"(b[0]), "r"(b[1]));
}

__device__ __forceinline__ void split_bf16(float2 f, uint32_t& hi, uint32_t& lo) {
    __nv_bfloat162 h2 = __float22bfloat162_rn(f);
    hi = *reinterpret_cast<uint32_t*>(&h2);
    float2 hf = __bfloat1622float2(h2);
    __nv_bfloat162 l2 = __float22bfloat162_rn(make_float2(f.x - hf.x, f.y - hf.y));
    lo = *reinterpret_cast<uint32_t*>(&l2);
}

__device__ __forceinline__ void cp_async16(void* smem_dst, const void* gmem_src) {
    uint32_t s = (uint32_t)__cvta_generic_to_shared(smem_dst);
    asm volatile("cp.async.cg.shared.global [%0], [%1], 16;\n"
                 :: "r"(s), "l"(gmem_src));
}
__device__ __forceinline__ void cp_async_commit() {
    asm volatile("cp.async.commit_group;\n" ::: "memory");
}
template <int NWait>
__device__ __forceinline__ void cp_async_wait() {
    asm volatile("cp.async.wait_group %0;\n" :: "n"(NWait) : "memory");
}

// FFMA2 helpers (layer-2 small GEMM)
__device__ __forceinline__ void ffma2(unsigned long long& c, unsigned long long a,
                                      unsigned long long b) {
    asm("fma.rn.f32x2 %0, %1, %2, %0;" : "+l"(c) : "l"(a), "l"(b));
}
__device__ __forceinline__ unsigned long long pack2(float x) {
    unsigned long long r;
    asm("mov.b64 %0, {%1, %1};" : "=l"(r) : "f"(x));
    return r;
}
__device__ __forceinline__ float2 unpack2(unsigned long long c) {
    float2 f;
    asm("mov.b64 {%0, %1}, %2;" : "=f"(f.x), "=f"(f.y) : "l"(c));
    return f;
}

// --------------------------- fused CSR build -------------------------------
__global__ void zero_all_kernel(int* c0, int* c1, int* c2) {
    int i = blockIdx.x * blockDim.x + threadIdx.x;
    if (i < N1) c0[i] = 0;
    else if (i < N1 + N2) c1[i - N1] = 0;
    else if (i < N1 + N2 + N3) c2[i - N1 - N2] = 0;
}

__global__ void hist_all_kernel(const int* d0, const int* d1, const int* d2,
                                int* c0, int* c1, int* c2) {
    int i = blockIdx.x * blockDim.x + threadIdx.x;
    if (i < E0) atomicAdd(&c0[d0[i]], 1);
    else if (i < E0 + E1) atomicAdd(&c1[d1[i - E0]], 1);
    else if (i < E0 + E1 + E2) atomicAdd(&c2[d2[i - E0 - E1]], 1);
}

__device__ void exscan_block(const int* __restrict__ cnt, int n,
                             int* __restrict__ off, int* __restrict__ cur) {
    __shared__ int wsum[32];
    __shared__ int tot_sh;
    __shared__ int carry_sh;
    const int t = threadIdx.x;
    const int lane = t & 31;
    const int w = t >> 5;
    if (t == 0) carry_sh = 0;
    __syncthreads();
    const int CH = 4096;
    for (int base = 0; base < n; base += CH) {
        int idx = base + t * 4;
        int v[4];
#pragma unroll
        for (int i = 0; i < 4; i++) v[i] = (idx + i < n) ? cnt[idx + i] : 0;
        int s = v[0] + v[1] + v[2] + v[3];
        int incl = s;
#pragma unroll
        for (int d = 1; d < 32; d <<= 1) {
            int o = __shfl_up_sync(0xffffffffu, incl, d);
            if (lane >= d) incl += o;
        }
        if (lane == 31) wsum[w] = incl;
        __syncthreads();
        if (w == 0) {
            int x = wsum[lane];
            int xi = x;
#pragma unroll
            for (int d = 1; d < 32; d <<= 1) {
                int o = __shfl_up_sync(0xffffffffu, xi, d);
                if (lane >= d) xi += o;
            }
            if (lane == 31) tot_sh = xi;
            wsum[lane] = xi - x;
        }
        __syncthreads();
        int carry = carry_sh;
        int run = carry + wsum[w] + (incl - s);
#pragma unroll
        for (int i = 0; i < 4; i++) {
            if (idx + i < n) { off[idx + i] = run; cur[idx + i] = run; }
            run += v[i];
        }
        __syncthreads();
        if (t == 0) carry_sh += tot_sh;
    }
    if (t == 0) off[n] = carry_sh;
}

__global__ void exscan3_kernel(const int* c0, int* o0, int* u0,
                               const int* c1, int* o1, int* u1,
                               const int* c2, int* o2, int* u2) {
    if (blockIdx.x == 0) exscan_block(c0, N1, o0, u0);
    else if (blockIdx.x == 1) exscan_block(c1, N2, o1, u1);
    else exscan_block(c2, N3, o2, u2);
}

__global__ void scatter_all_kernel(const int* s0, const int* d0, int* u0, int* e0,
                                   const int* s1, const int* d1, int* u1, int* e1,
                                   const int* s2, const int* d2, int* u2, int* e2) {
    int i = blockIdx.x * blockDim.x + threadIdx.x;
    if (i < E0) {
        int p = atomicAdd(&u0[d0[i]], 1); e0[p] = s0[i];
    } else if (i < E0 + E1) {
        int j = i - E0;
        int p = atomicAdd(&u1[d1[j]], 1); e1[p] = s1[j];
    } else if (i < E0 + E1 + E2) {
        int j = i - E0 - E1;
        int p = atomicAdd(&u2[d2[j]], 1); e2[p] = s2[j];
    }
}

// ------------------------- warp-per-dst mean aggregation -------------------
template <int D>
__global__ void aggregate_kernel(const float* __restrict__ X,
                                 const int* __restrict__ off,
                                 const int* __restrict__ srcs,
                                 float* __restrict__ out, int n_dst) {
    int g = (blockIdx.x * blockDim.x + threadIdx.x) >> 5;
    if (g >= n_dst) return;
    int lane = threadIdx.x & 31;
    int beg = off[g], end = off[g + 1];
    float4 a0 = make_float4(0.f, 0.f, 0.f, 0.f);
    float4 a1 = make_float4(0.f, 0.f, 0.f, 0.f);
    int j = beg;
    for (; j + 1 < end; j += 2) {
        int s0 = srcs[j], s1 = srcs[j + 1];
        const float4* r0 = (const float4*)(X + (size_t)s0 * D);
        const float4* r1 = (const float4*)(X + (size_t)s1 * D);
        float4 v0 = r0[lane];
        float4 v1 = r1[lane];
        a0.x += v0.x + v1.x; a0.y += v0.y + v1.y;
        a0.z += v0.z + v1.z; a0.w += v0.w + v1.w;
        if (D == 256) {
            float4 u0 = r0[lane + 32];
            float4 u1 = r1[lane + 32];
            a1.x += u0.x + u1.x; a1.y += u0.y + u1.y;
            a1.z += u0.z + u1.z; a1.w += u0.w + u1.w;
        }
    }
    if (j < end) {
        int s = srcs[j];
        const float4* row = (const float4*)(X + (size_t)s * D);
        float4 v = row[lane];
        a0.x += v.x; a0.y += v.y; a0.z += v.z; a0.w += v.w;
        if (D == 256) {
            float4 u = row[lane + 32];
            a1.x += u.x; a1.y += u.y; a1.z += u.z; a1.w += u.w;
        }
    }
    int c = end - beg;
    float inv = 1.0f / (float)(c > 0 ? c : 1);
    float4* o = (float4*)(out + (size_t)g * D);
    o[lane] = make_float4(a0.x * inv, a0.y * inv, a0.z * inv, a0.w * inv);
    if (D == 256)
        o[lane + 32] = make_float4(a1.x * inv, a1.y * inv, a1.z * inv, a1.w * inv);
}

// ---------------- weight transpose + bf16 hi/lo split ----------------------
// Wcat[K][N] (rows 0..K1-1 = Wl, K1..K-1 = Wr) -> Wt_hi/Wt_lo [N][K] bf16.
__global__ void prep_w_kernel(const float* __restrict__ Wl, const float* __restrict__ Wr,
                              int K1, int K, int N,
                              __nv_bfloat16* __restrict__ hi,
                              __nv_bfloat16* __restrict__ lo) {
    int idx = blockIdx.x * blockDim.x + threadIdx.x;
    if (idx >= N * K) return;
    int n = idx / K, k = idx % K;
    float v = (k < K1) ? Wl[(size_t)k * N + n] : Wr[(size_t)(k - K1) * N + n];
    __nv_bfloat16 h = __float2bfloat16_rn(v);
    hi[(size_t)n * K + k] = h;
    lo[(size_t)n * K + k] = __float2bfloat16_rn(v - __bfloat162float(h));
}

// ----------------------- bf16x3 mma.sync SAGE GEMM -------------------------
// C[M,N] = relu?( [Aagg(K1 cols) | Adst] @ Wt^T + bias ).
// CTA tile 128 x N(=256), 8 warps (4m x 2n), warp tile 32x128.
// A fp32 in smem (split to bf16 in regs); B bf16 hi/lo staged via cp.async.
template <int N, bool RELU>
__global__ void __launch_bounds__(256, 1)
sage_mma_gemm(const float* __restrict__ Aagg, int K1,
              const float* __restrict__ Adst, int ldDst, int K,
              const __nv_bfloat16* __restrict__ Wth,
              const __nv_bfloat16* __restrict__ Wtl,
              const float* __restrict__ bias, float* __restrict__ C) {
    extern __shared__ char smem[];
    constexpr int ASTR = 36;                   // floats per A row
    constexpr int BSTR = 40;                   // halves per B row
    constexpr int ABYTES = 128 * ASTR * 4;     // 18432
    constexpr int BBYTES = N * BSTR * 2;       // 20480 for N=256
    float* As[2] = {(float*)smem, (float*)(smem + ABYTES)};
    __nv_bfloat16* Bh[2] = {(__nv_bfloat16*)(smem + 2 * ABYTES),
                            (__nv_bfloat16*)(smem + 2 * ABYTES + BBYTES)};
    __nv_bfloat16* Bl[2] = {(__nv_bfloat16*)(smem + 2 * ABYTES + 2 * BBYTES),
                            (__nv_bfloat16*)(smem + 2 * ABYTES + 3 * BBYTES)};

    const int tid = threadIdx.x;
    const int wid = tid >> 5;
    const int lane = tid & 31;
    const int g = lane >> 2;
    const int t = lane & 3;
    const int wm = (wid & 3) * 32;
    const int wn = (wid >> 2) * (N / 2);
    const int rowBase = blockIdx.x * 128;
    const int NC = K / 32;
    constexpr int NIN = N / 16;                // 8-col groups per warp

    float acc[2][NIN][4];
#pragma unroll
    for (int im = 0; im < 2; im++)
#pragma unroll
        for (int i = 0; i < NIN; i++)
#pragma unroll
            for (int q = 0; q < 4; q++) acc[im][i][q] = 0.f;

    auto issue_chunk = [&](int kc, int b) {
        const int acol = kc * 32;
        const bool inAgg = acol < K1;
        const float* abase = inAgg ? (Aagg + acol) : (Adst + (acol - K1));
        const int ald = inAgg ? K1 : ldDst;
#pragma unroll
        for (int p = 0; p < 4; p++) {
            int idx = p * 256 + tid;
            int r = idx >> 3, c4 = idx & 7;
            cp_async16(&As[b][r * ASTR + c4 * 4],
                       abase + (size_t)(rowBase + r) * ald + c4 * 4);
        }
#pragma unroll
        for (int p = 0; p < N / 64; p++) {     // N rows * 4 sixteen-byte pieces
            int idx = p * 256 + tid;
            int r = idx >> 2, c8 = idx & 3;
            cp_async16(&Bh[b][r * BSTR + c8 * 8],
                       Wth + (size_t)r * K + acol + c8 * 8);
            cp_async16(&Bl[b][r * BSTR + c8 * 8],
                       Wtl + (size_t)r * K + acol + c8 * 8);
        }
        cp_async_commit();
    };

    issue_chunk(0, 0);

    for (int kc = 0; kc < NC; kc++) {
        const int b = kc & 1;
        const bool more = (kc + 1 < NC);
        if (more) issue_chunk(kc + 1, b ^ 1);
        if (more) cp_async_wait<1>(); else cp_async_wait<0>();
        __syncthreads();

        const float* Ab = As[b];
        const __nv_bfloat16* Bhb = Bh[b];
        const __nv_bfloat16* Blb = Bl[b];
#pragma unroll
        for (int s = 0; s < 2; s++) {          // two k16 steps per 32-chunk
            const int kb = s * 16;
            uint32_t ah[2][4], al[2][4];
#pragma unroll
            for (int im = 0; im < 2; im++) {
                const int r0 = wm + im * 16 + g;
                float2 f0 = *(const float2*)&Ab[r0 * ASTR + kb + 2 * t];
                float2 f1 = *(const float2*)&Ab[(r0 + 8) * ASTR + kb + 2 * t];
                float2 f2 = *(const float2*)&Ab[r0 * ASTR + kb + 8 + 2 * t];
                float2 f3 = *(const float2*)&Ab[(r0 + 8) * ASTR + kb + 8 + 2 * t];
                split_bf16(f0, ah[im][0], al[im][0]);
                split_bf16(f1, ah[im][1], al[im][1]);
                split_bf16(f2, ah[im][2], al[im][2]);
                split_bf16(f3, ah[im][3], al[im][3]);
            }
#pragma unroll
            for (int i = 0; i < NIN; i++) {
                const int n = wn + i * 8 + g;
                uint32_t bh[2], bl[2];
                bh[0] = *(const uint32_t*)&Bhb[n * BSTR + kb + 2 * t];
                bh[1] = *(const uint32_t*)&Bhb[n * BSTR + kb + 8 + 2 * t];
                bl[0] = *(const uint32_t*)&Blb[n * BSTR + kb + 2 * t];
                bl[1] = *(const uint32_t*)&Blb[n * BSTR + kb + 8 + 2 * t];
                mma_bf16(acc[0][i], ah[0], bh);
                mma_bf16(acc[1][i], ah[1], bh);
                mma_bf16(acc[0][i], ah[0], bl);
                mma_bf16(acc[1][i], ah[1], bl);
                mma_bf16(acc[0][i], al[0], bh);
                mma_bf16(acc[1][i], al[1], bh);
            }
        }
        __syncthreads();
    }

    // ---- epilogue ----
#pragma unroll
    for (int i = 0; i < NIN; i++) {
        const int col = wn + i * 8 + 2 * t;
        const float b0 = __ldg(bias + col);
        const float b1 = __ldg(bias + col + 1);
#pragma unroll
        for (int im = 0; im < 2; im++) {
            const int row = rowBase + wm + im * 16 + g;
            float v0 = acc[im][i][0] + b0;
            float v1 = acc[im][i][1] + b1;
            float v2 = acc[im][i][2] + b0;
            float v3 = acc[im][i][3] + b1;
            if (RELU) {
                v0 = fmaxf(v0, 0.f); v1 = fmaxf(v1, 0.f);
                v2 = fmaxf(v2, 0.f); v3 = fmaxf(v3, 0.f);
            }
            *(float2*)&C[(size_t)row * N + col] = make_float2(v0, v1);
            *(float2*)&C[(size_t)(row + 8) * N + col] = make_float2(v2, v3);
        }
    }
}

// ----------------------- FFMA2 GEMM (layer 2 only) -------------------------
template <int BM, int BN, int BK, int TM, int TN, bool RELU>
__global__ void __launch_bounds__((BM / TM) * (BN / TN))
sage_gemm_kernel(const float* __restrict__ Aagg, int K1,
                 const float* __restrict__ Adst, int K2, int ldDst,
                 const float* __restrict__ Wl, const float* __restrict__ Wr,
                 const float* __restrict__ bias,
                 float* __restrict__ C, int N) {
    constexpr int THREADS = (BM / TM) * (BN / TN);
    constexpr int LDA = BM + 4;
    __shared__ float As[BK][LDA];
    __shared__ float Bs[BK][BN];

    const int tid = threadIdx.x;
    const int tx = tid % (BN / TN);
    const int ty = tid / (BN / TN);
    const int rowBase = blockIdx.y * BM;
    const int colBase = blockIdx.x * BN;
    const int K = K1 + K2;

    unsigned long long c2[TM / 2][TN];
#pragma unroll
    for (int i = 0; i < TM / 2; i++)
#pragma unroll
        for (int j = 0; j < TN; j++) c2[i][j] = 0ull;

    constexpr int ACOLS4 = BK / 4;
    const int acol4 = tid % ACOLS4;
    const int arow = tid / ACOLS4;
    constexpr int AROWS_PER = THREADS / ACOLS4;
    constexpr int APASS = BM / AROWS_PER;

    constexpr int BCOLS4 = BN / 4;
    const int bcol4 = tid % BCOLS4;
    const int brow = tid / BCOLS4;
    constexpr int BROWS_PER = THREADS / BCOLS4;
    constexpr int BPASS = BK / BROWS_PER;

    for (int k0 = 0; k0 < K; k0 += BK) {
        const bool inAgg = (k0 < K1);
#pragma unroll
        for (int p = 0; p < APASS; p++) {
            int r = arow + p * AROWS_PER;
            int grow = rowBase + r;
            const float* src = inAgg
                ? (Aagg + (size_t)grow * K1 + k0 + acol4 * 4)
                : (Adst + (size_t)grow * ldDst + (k0 - K1) + acol4 * 4);
            float4 v = *(const float4*)src;
            As[acol4 * 4 + 0][r] = v.x;
            As[acol4 * 4 + 1][r] = v.y;
            As[acol4 * 4 + 2][r] = v.z;
            As[acol4 * 4 + 3][r] = v.w;
        }
#pragma unroll
        for (int p = 0; p < BPASS; p++) {
            int r = brow + p * BROWS_PER;
            int kg = k0 + r;
            const float* src = (kg < K1)
                ? (Wl + (size_t)kg * N + colBase + bcol4 * 4)
                : (Wr + (size_t)(kg - K1) * N + colBase + bcol4 * 4);
            *(float4*)&Bs[r][bcol4 * 4] = *(const float4*)src;
        }
        __syncthreads();
#pragma unroll
        for (int kk = 0; kk < BK; kk++) {
            unsigned long long a2[TM / 2];
#pragma unroll
            for (int i = 0; i < TM / 2; i++)
                a2[i] = *(const unsigned long long*)&As[kk][ty * TM + 2 * i];
            unsigned long long bb[TN];
#pragma unroll
            for (int j = 0; j < TN; j++) bb[j] = pack2(Bs[kk][tx * TN + j]);
#pragma unroll
            for (int i = 0; i < TM / 2; i++)
#pragma unroll
                for (int j = 0; j < TN; j++) ffma2(c2[i][j], a2[i], bb[j]);
        }
        __syncthreads();
    }
#pragma unroll
    for (int j = 0; j < TN; j++) {
        int n = colBase + tx * TN + j;
        float bj = bias[n];
#pragma unroll
        for (int i = 0; i < TM / 2; i++) {
            float2 v = unpack2(c2[i][j]);
            float lo = v.x + bj;
            float hi = v.y + bj;
            if (RELU) { lo = fmaxf(lo, 0.f); hi = fmaxf(hi, 0.f); }
            int m = rowBase + ty * TM + 2 * i;
            C[(size_t)m * N + n] = lo;
            C[(size_t)(m + 1) * N + n] = hi;
        }
    }
}

// ------------------------------- launcher ----------------------------------
static inline int cdiv(int a, int b) { return (a + b - 1) / b; }

extern "C" void kernel_launch(void* const* d_in, const int* in_sizes, int n_in,
                              void* d_out, int out_size) {
    const float* x   = (const float*)d_in[0];
    const float* Wl0 = (const float*)d_in[1];
    const float* bl0 = (const float*)d_in[2];
    const float* Wr0 = (const float*)d_in[3];
    const float* Wl1 = (const float*)d_in[4];
    const float* bl1 = (const float*)d_in[5];
    const float* Wr1 = (const float*)d_in[6];
    const float* Wl2 = (const float*)d_in[7];
    const float* bl2 = (const float*)d_in[8];
    const float* Wr2 = (const float*)d_in[9];
    const int* es0 = (const int*)d_in[10];
    const int* ed0 = (const int*)d_in[11];
    const int* es1 = (const int*)d_in[12];
    const int* ed1 = (const int*)d_in[13];
    const int* es2 = (const int*)d_in[14];
    const int* ed2 = (const int*)d_in[15];
    float* out = (float*)d_out;

    float *mean0, *h0, *mean1, *h1, *mean2;
    __nv_bfloat16 *wt0h, *wt0l, *wt1h, *wt1l;
    int *cnt0, *off0, *cur0, *esrc0;
    int *cnt1, *off1, *cur1, *esrc1;
    int *cnt2, *off2, *cur2, *esrc2;
    cudaGetSymbolAddress((void**)&mean0, g_mean0);
    cudaGetSymbolAddress((void**)&h0, g_h0);
    cudaGetSymbolAddress((void**)&mean1, g_mean1);
    cudaGetSymbolAddress((void**)&h1, g_h1);
    cudaGetSymbolAddress((void**)&mean2, g_mean2);
    cudaGetSymbolAddress((void**)&wt0h, g_wt0h);
    cudaGetSymbolAddress((void**)&wt0l, g_wt0l);
    cudaGetSymbolAddress((void**)&wt1h, g_wt1h);
    cudaGetSymbolAddress((void**)&wt1l, g_wt1l);
    cudaGetSymbolAddress((void**)&cnt0, g_cnt0);
    cudaGetSymbolAddress((void**)&off0, g_off0);
    cudaGetSymbolAddress((void**)&cur0, g_cur0);
    cudaGetSymbolAddress((void**)&esrc0, g_esrc0);
    cudaGetSymbolAddress((void**)&cnt1, g_cnt1);
    cudaGetSymbolAddress((void**)&off1, g_off1);
    cudaGetSymbolAddress((void**)&cur1, g_cur1);
    cudaGetSymbolAddress((void**)&esrc1, g_esrc1);
    cudaGetSymbolAddress((void**)&cnt2, g_cnt2);
    cudaGetSymbolAddress((void**)&off2, g_off2);
    cudaGetSymbolAddress((void**)&cur2, g_cur2);
    cudaGetSymbolAddress((void**)&esrc2, g_esrc2);

    constexpr int SMEM_MMA = 2 * 128 * 36 * 4 + 4 * 256 * 40 * 2;  // 118784
    cudaFuncSetAttribute(sage_mma_gemm<256, true>,
                         cudaFuncAttributeMaxDynamicSharedMemorySize, SMEM_MMA);
    cudaFuncSetAttribute(sage_mma_gemm<256, false>,
                         cudaFuncAttributeMaxDynamicSharedMemorySize, SMEM_MMA);

    // weight transpose + split (independent of graph work)
    prep_w_kernel<<<cdiv(256 * 256, 256), 256>>>(Wl0, Wr0, D_IN, 2 * D_IN, D_H, wt0h, wt0l);
    prep_w_kernel<<<cdiv(256 * 512, 256), 256>>>(Wl1, Wr1, D_H, 2 * D_H, D_H, wt1h, wt1l);

    // fused CSR build for all three layers
    zero_all_kernel<<<cdiv(N1 + N2 + N3, 256), 256>>>(cnt0, cnt1, cnt2);
    hist_all_kernel<<<cdiv(E0 + E1 + E2, 256), 256>>>(ed0, ed1, ed2, cnt0, cnt1, cnt2);
    exscan3_kernel<<<3, 1024>>>(cnt0, off0, cur0, cnt1, off1, cur1, cnt2, off2, cur2);
    scatter_all_kernel<<<cdiv(E0 + E1 + E2, 256), 256>>>(
        es0, ed0, cur0, esrc0, es1, ed1, cur1, esrc1, es2, ed2, cur2, esrc2);

    // ---------------- layer 0 ----------------
    aggregate_kernel<128><<<cdiv(N1 * 32, 256), 256>>>(x, off0, esrc0, mean0, N1);
    sage_mma_gemm<256, true><<<N1 / 128, 256, SMEM_MMA>>>(
        mean0, D_IN, x, D_IN, 2 * D_IN, wt0h, wt0l, bl0, h0);

    // ---------------- layer 1 ----------------
    aggregate_kernel<256><<<cdiv(N2 * 32, 256), 256>>>(h0, off1, esrc1, mean1, N2);
    sage_mma_gemm<256, false><<<N2 / 128, 256, SMEM_MMA>>>(
        mean1, D_H, h0, D_H, 2 * D_H, wt1h, wt1l, bl1, h1);

    // ---------------- layer 2 ----------------
    aggregate_kernel<256><<<cdiv(N3 * 32, 256), 256>>>(h1, off2, esrc2, mean2, N3);
    sage_gemm_kernel<64, 64, 16, 4, 4, true>
        <<<dim3(D_OUT / 64, N3 / 64), 256>>>(mean2, D_H, h1, D_H, D_H,
                                             Wl2, Wr2, bl2, out, D_OUT);
}

// round 6
// speedup vs baseline: 2.2555x; 1.1966x over previous
#include <cuda_runtime.h>
#include <cuda_bf16.h>
#include <cstdint>

// ---------------------------------------------------------------------------
// GNN_37082747634058: 3-layer GraphSAGE(mean) forward.
//   fused CSR build (parallel 3-phase scan) -> per layer: warp-per-dst mean ->
//   GEMM out = relu?( [mean | x_dst] @ [Wl;Wr] + bl )
// All GEMMs: mma.sync m16n8k16 bf16, 3-term split (hi*hi + hi*lo + lo*hi,
// fp32 accum). Weights pre-split to bf16 hi/lo. cp.async double buffered.
// ---------------------------------------------------------------------------

#define N0 1363968
#define N1 123904
#define N2 11264
#define N3 1024
#define E0 1239040
#define E1 112640
#define E2 10240
#define D_IN 128
#define D_H  256
#define D_OUT 64

#define NTOT (N1 + N2 + N3)      // 136192
#define EPB 4096                 // elements per scan block
#define NB  ((NTOT + EPB - 1) / EPB)  // 34

// ------------------------- static device scratch ---------------------------
__device__ float g_mean0[(size_t)N1 * D_IN];
__device__ float g_h0   [(size_t)N1 * D_H];
__device__ float g_mean1[(size_t)N2 * D_H];
__device__ float g_h1   [(size_t)N2 * D_H];
__device__ float g_mean2[(size_t)N3 * D_H];

__device__ __nv_bfloat16 g_wt0h[256 * 256], g_wt0l[256 * 256];
__device__ __nv_bfloat16 g_wt1h[256 * 512], g_wt1l[256 * 512];
__device__ __nv_bfloat16 g_wt2h[64 * 512],  g_wt2l[64 * 512];

__device__ int g_cnt0[N1], g_off0[N1 + 1], g_cur0[N1], g_esrc0[E0];
__device__ int g_cnt1[N2], g_off1[N2 + 1], g_cur1[N2], g_esrc1[E1];
__device__ int g_cnt2[N3], g_off2[N3 + 1], g_cur2[N3], g_esrc2[E2];
__device__ int g_bsum[NB + 1], g_bpre[NB + 1];

// ------------------------------ helpers ------------------------------------
__device__ __forceinline__ void mma_bf16(float (&c)[4], const uint32_t (&a)[4],
                                         const uint32_t (&b)[2]) {
    asm volatile(
        "mma.sync.aligned.m16n8k16.row.col.f32.bf16.bf16.f32 "
        "{%0,%1,%2,%3}, {%4,%5,%6,%7}, {%8,%9}, {%0,%1,%2,%3};"
        : "+f"(c[0]), "+f"(c[1]), "+f"(c[2]), "+f"(c[3])
        : "r"(a[0]), "r"(a[1]), "r"(a[2]), "r"(a[3]), "r"(b[0]), "r"(b[1]));
}

__device__ __forceinline__ void split_bf16(float2 f, uint32_t& hi, uint32_t& lo) {
    __nv_bfloat162 h2 = __float22bfloat162_rn(f);
    hi = *reinterpret_cast<uint32_t*>(&h2);
    float2 hf = __bfloat1622float2(h2);
    __nv_bfloat162 l2 = __float22bfloat162_rn(make_float2(f.x - hf.x, f.y - hf.y));
    lo = *reinterpret_cast<uint32_t*>(&l2);
}

__device__ __forceinline__ void cp_async16(void* smem_dst, const void* gmem_src) {
    uint32_t s = (uint32_t)__cvta_generic_to_shared(smem_dst);
    asm volatile("cp.async.cg.shared.global [%0], [%1], 16;\n"
                 :: "r"(s), "l"(gmem_src));
}
__device__ __forceinline__ void cp_async_commit() {
    asm volatile("cp.async.commit_group;\n" ::: "memory");
}
template <int NWait>
__device__ __forceinline__ void cp_async_wait() {
    asm volatile("cp.async.wait_group %0;\n" :: "n"(NWait) : "memory");
}

// --------------------------- fused CSR build -------------------------------
__global__ void zero_all_kernel(int* c0, int* c1, int* c2) {
    int i = blockIdx.x * blockDim.x + threadIdx.x;
    if (i < N1) c0[i] = 0;
    else if (i < N1 + N2) c1[i - N1] = 0;
    else if (i < N1 + N2 + N3) c2[i - N1 - N2] = 0;
}

__global__ void hist_all_kernel(const int* d0, const int* d1, const int* d2,
                                int* c0, int* c1, int* c2) {
    int i = blockIdx.x * blockDim.x + threadIdx.x;
    if (i < E0) atomicAdd(&c0[d0[i]], 1);
    else if (i < E0 + E1) atomicAdd(&c1[d1[i - E0]], 1);
    else if (i < E0 + E1 + E2) atomicAdd(&c2[d2[i - E0 - E1]], 1);
}

__device__ __forceinline__ int cnt_cat(const int* c0, const int* c1, const int* c2,
                                       int i) {
    if (i < N1) return c0[i];
    if (i < N1 + N2) return c1[i - N1];
    return c2[i - N1 - N2];
}

// phase A: per-block totals of the concatenated count array
__global__ void scanA_kernel(const int* c0, const int* c1, const int* c2,
                             int* bsum) {
    __shared__ int wsum[32];
    const int t = threadIdx.x, lane = t & 31, w = t >> 5;
    const int base = blockIdx.x * EPB + t * 4;
    int s = 0;
#pragma unroll
    for (int i = 0; i < 4; i++) {
        int idx = base + i;
        if (idx < NTOT) s += cnt_cat(c0, c1, c2, idx);
    }
#pragma unroll
    for (int d = 16; d > 0; d >>= 1) s += __shfl_down_sync(0xffffffffu, s, d);
    if (lane == 0) wsum[w] = s;
    __syncthreads();
    if (w == 0) {
        int v = wsum[lane];
#pragma unroll
        for (int d = 16; d > 0; d >>= 1) v += __shfl_down_sync(0xffffffffu, v, d);
        if (lane == 0) bsum[blockIdx.x] = v;
    }
}

// phase B: exclusive scan of NB block totals (tiny)
__global__ void scanB_kernel(const int* bsum, int* bpre) {
    if (threadIdx.x == 0) {
        int run = 0;
        for (int b = 0; b < NB; b++) { bpre[b] = run; run += bsum[b]; }
    }
}

// phase C: in-block exclusive scan + block prefix, routed to per-layer arrays
__global__ void scanC_kernel(const int* c0, const int* c1, const int* c2,
                             const int* bpre,
                             int* o0, int* u0, int* o1, int* u1,
                             int* o2, int* u2) {
    __shared__ int wsum[32];
    const int t = threadIdx.x, lane = t & 31, w = t >> 5;
    const int base = blockIdx.x * EPB + t * 4;
    int v[4];
#pragma unroll
    for (int i = 0; i < 4; i++) {
        int idx = base + i;
        v[i] = (idx < NTOT) ? cnt_cat(c0, c1, c2, idx) : 0;
    }
    int s = v[0] + v[1] + v[2] + v[3];
    int incl = s;
#pragma unroll
    for (int d = 1; d < 32; d <<= 1) {
        int o = __shfl_up_sync(0xffffffffu, incl, d);
        if (lane >= d) incl += o;
    }
    if (lane == 31) wsum[w] = incl;
    __syncthreads();
    if (w == 0) {
        int x = wsum[lane];
        int xi = x;
#pragma unroll
        for (int d = 1; d < 32; d <<= 1) {
            int o = __shfl_up_sync(0xffffffffu, xi, d);
            if (lane >= d) xi += o;
        }
        wsum[lane] = xi - x;
    }
    __syncthreads();
    int run = bpre[blockIdx.x] + wsum[w] + (incl - s);
#pragma unroll
    for (int i = 0; i < 4; i++) {
        int idx = base + i;
        if (idx < NTOT) {
            if (idx < N1)            { o0[idx] = run;            u0[idx] = run; }
            else if (idx < N1 + N2)  { int j = idx - N1;
                                       o1[j] = run - E0;         u1[j] = run - E0; }
            else                     { int j = idx - N1 - N2;
                                       o2[j] = run - E0 - E1;    u2[j] = run - E0 - E1; }
        }
        run += v[i];
    }
    if (blockIdx.x == 0 && t == 0) {
        o0[N1] = E0; o1[N2] = E1; o2[N3] = E2;
    }
}

__global__ void scatter_all_kernel(const int* s0, const int* d0, int* u0, int* e0,
                                   const int* s1, const int* d1, int* u1, int* e1,
                                   const int* s2, const int* d2, int* u2, int* e2) {
    int i = blockIdx.x * blockDim.x + threadIdx.x;
    if (i < E0) {
        int p = atomicAdd(&u0[d0[i]], 1); e0[p] = s0[i];
    } else if (i < E0 + E1) {
        int j = i - E0;
        int p = atomicAdd(&u1[d1[j]], 1); e1[p] = s1[j];
    } else if (i < E0 + E1 + E2) {
        int j = i - E0 - E1;
        int p = atomicAdd(&u2[d2[j]], 1); e2[p] = s2[j];
    }
}

// ------------------------- warp-per-dst mean aggregation -------------------
template <int D>
__global__ void aggregate_kernel(const float* __restrict__ X,
                                 const int* __restrict__ off,
                                 const int* __restrict__ srcs,
                                 float* __restrict__ out, int n_dst) {
    int g = (blockIdx.x * blockDim.x + threadIdx.x) >> 5;
    if (g >= n_dst) return;
    int lane = threadIdx.x & 31;
    int beg = off[g], end = off[g + 1];
    float4 a0 = make_float4(0.f, 0.f, 0.f, 0.f);
    float4 a1 = make_float4(0.f, 0.f, 0.f, 0.f);
    int j = beg;
    for (; j + 3 < end; j += 4) {
        int s0 = srcs[j], s1 = srcs[j + 1], s2 = srcs[j + 2], s3 = srcs[j + 3];
        const float4* r0 = (const float4*)(X + (size_t)s0 * D);
        const float4* r1 = (const float4*)(X + (size_t)s1 * D);
        const float4* r2 = (const float4*)(X + (size_t)s2 * D);
        const float4* r3 = (const float4*)(X + (size_t)s3 * D);
        float4 v0 = r0[lane], v1 = r1[lane], v2 = r2[lane], v3 = r3[lane];
        a0.x += (v0.x + v1.x) + (v2.x + v3.x);
        a0.y += (v0.y + v1.y) + (v2.y + v3.y);
        a0.z += (v0.z + v1.z) + (v2.z + v3.z);
        a0.w += (v0.w + v1.w) + (v2.w + v3.w);
        if (D == 256) {
            float4 u0 = r0[lane + 32], u1 = r1[lane + 32];
            float4 u2 = r2[lane + 32], u3 = r3[lane + 32];
            a1.x += (u0.x + u1.x) + (u2.x + u3.x);
            a1.y += (u0.y + u1.y) + (u2.y + u3.y);
            a1.z += (u0.z + u1.z) + (u2.z + u3.z);
            a1.w += (u0.w + u1.w) + (u2.w + u3.w);
        }
    }
    for (; j < end; j++) {
        int s = srcs[j];
        const float4* row = (const float4*)(X + (size_t)s * D);
        float4 v = row[lane];
        a0.x += v.x; a0.y += v.y; a0.z += v.z; a0.w += v.w;
        if (D == 256) {
            float4 u = row[lane + 32];
            a1.x += u.x; a1.y += u.y; a1.z += u.z; a1.w += u.w;
        }
    }
    int c = end - beg;
    float inv = 1.0f / (float)(c > 0 ? c : 1);
    float4* o = (float4*)(out + (size_t)g * D);
    o[lane] = make_float4(a0.x * inv, a0.y * inv, a0.z * inv, a0.w * inv);
    if (D == 256)
        o[lane + 32] = make_float4(a1.x * inv, a1.y * inv, a1.z * inv, a1.w * inv);
}

// ---------------- weight transpose + bf16 hi/lo split ----------------------
__global__ void prep_w_kernel(const float* __restrict__ Wl, const float* __restrict__ Wr,
                              int K1, int K, int N,
                              __nv_bfloat16* __restrict__ hi,
                              __nv_bfloat16* __restrict__ lo) {
    int idx = blockIdx.x * blockDim.x + threadIdx.x;
    if (idx >= N * K) return;
    int n = idx / K, k = idx % K;
    float v = (k < K1) ? Wl[(size_t)k * N + n] : Wr[(size_t)(k - K1) * N + n];
    __nv_bfloat16 h = __float2bfloat16_rn(v);
    hi[(size_t)n * K + k] = h;
    lo[(size_t)n * K + k] = __float2bfloat16_rn(v - __bfloat162float(h));
}

// ----------------------- bf16x3 mma.sync SAGE GEMM -------------------------
// C[M,N] = relu?( [Aagg(K1 cols) | Adst] @ Wt^T + bias ).
// CTA tile 128 x N, 8 warps (4m x 2n). A fp32 in smem (reg split);
// B bf16 hi/lo via cp.async, double buffered.
template <int N, bool RELU>
__global__ void __launch_bounds__(256, 1)
sage_mma_gemm(const float* __restrict__ Aagg, int K1,
              const float* __restrict__ Adst, int ldDst, int K,
              const __nv_bfloat16* __restrict__ Wth,
              const __nv_bfloat16* __restrict__ Wtl,
              const float* __restrict__ bias, float* __restrict__ C) {
    extern __shared__ char smem[];
    constexpr int ASTR = 36;
    constexpr int BSTR = 40;
    constexpr int ABYTES = 128 * ASTR * 4;
    constexpr int BBYTES = N * BSTR * 2;
    float* As[2] = {(float*)smem, (float*)(smem + ABYTES)};
    __nv_bfloat16* Bh[2] = {(__nv_bfloat16*)(smem + 2 * ABYTES),
                            (__nv_bfloat16*)(smem + 2 * ABYTES + BBYTES)};
    __nv_bfloat16* Bl[2] = {(__nv_bfloat16*)(smem + 2 * ABYTES + 2 * BBYTES),
                            (__nv_bfloat16*)(smem + 2 * ABYTES + 3 * BBYTES)};

    const int tid = threadIdx.x;
    const int wid = tid >> 5;
    const int lane = tid & 31;
    const int g = lane >> 2;
    const int t = lane & 3;
    const int wm = (wid & 3) * 32;
    const int wn = (wid >> 2) * (N / 2);
    const int rowBase = blockIdx.x * 128;
    const int NC = K / 32;
    constexpr int NIN = N / 16;

    float acc[2][NIN][4];
#pragma unroll
    for (int im = 0; im < 2; im++)
#pragma unroll
        for (int i = 0; i < NIN; i++)
#pragma unroll
            for (int q = 0; q < 4; q++) acc[im][i][q] = 0.f;

    auto issue_chunk = [&](int kc, int b) {
        const int acol = kc * 32;
        const bool inAgg = acol < K1;
        const float* abase = inAgg ? (Aagg + acol) : (Adst + (acol - K1));
        const int ald = inAgg ? K1 : ldDst;
#pragma unroll
        for (int p = 0; p < 4; p++) {
            int idx = p * 256 + tid;
            int r = idx >> 3, c4 = idx & 7;
            cp_async16(&As[b][r * ASTR + c4 * 4],
                       abase + (size_t)(rowBase + r) * ald + c4 * 4);
        }
#pragma unroll
        for (int p = 0; p < N / 64; p++) {
            int idx = p * 256 + tid;
            int r = idx >> 2, c8 = idx & 3;
            cp_async16(&Bh[b][r * BSTR + c8 * 8],
                       Wth + (size_t)r * K + acol + c8 * 8);
            cp_async16(&Bl[b][r * BSTR + c8 * 8],
                       Wtl + (size_t)r * K + acol + c8 * 8);
        }
        cp_async_commit();
    };

    issue_chunk(0, 0);

    for (int kc = 0; kc < NC; kc++) {
        const int b = kc & 1;
        const bool more = (kc + 1 < NC);
        if (more) issue_chunk(kc + 1, b ^ 1);
        if (more) cp_async_wait<1>(); else cp_async_wait<0>();
        __syncthreads();

        const float* Ab = As[b];
        const __nv_bfloat16* Bhb = Bh[b];
        const __nv_bfloat16* Blb = Bl[b];
#pragma unroll
        for (int s = 0; s < 2; s++) {
            const int kb = s * 16;
            uint32_t ah[2][4], al[2][4];
#pragma unroll
            for (int im = 0; im < 2; im++) {
                const int r0 = wm + im * 16 + g;
                float2 f0 = *(const float2*)&Ab[r0 * ASTR + kb + 2 * t];
                float2 f1 = *(const float2*)&Ab[(r0 + 8) * ASTR + kb + 2 * t];
                float2 f2 = *(const float2*)&Ab[r0 * ASTR + kb + 8 + 2 * t];
                float2 f3 = *(const float2*)&Ab[(r0 + 8) * ASTR + kb + 8 + 2 * t];
                split_bf16(f0, ah[im][0], al[im][0]);
                split_bf16(f1, ah[im][1], al[im][1]);
                split_bf16(f2, ah[im][2], al[im][2]);
                split_bf16(f3, ah[im][3], al[im][3]);
            }
#pragma unroll
            for (int i = 0; i < NIN; i++) {
                const int n = wn + i * 8 + g;
                uint32_t bh[2], bl[2];
                bh[0] = *(const uint32_t*)&Bhb[n * BSTR + kb + 2 * t];
                bh[1] = *(const uint32_t*)&Bhb[n * BSTR + kb + 8 + 2 * t];
                bl[0] = *(const uint32_t*)&Blb[n * BSTR + kb + 2 * t];
                bl[1] = *(const uint32_t*)&Blb[n * BSTR + kb + 8 + 2 * t];
                mma_bf16(acc[0][i], ah[0], bh);
                mma_bf16(acc[1][i], ah[1], bh);
                mma_bf16(acc[0][i], ah[0], bl);
                mma_bf16(acc[1][i], ah[1], bl);
                mma_bf16(acc[0][i], al[0], bh);
                mma_bf16(acc[1][i], al[1], bh);
            }
        }
        __syncthreads();
    }

    // ---- epilogue ----
#pragma unroll
    for (int i = 0; i < NIN; i++) {
        const int col = wn + i * 8 + 2 * t;
        const float b0 = __ldg(bias + col);
        const float b1 = __ldg(bias + col + 1);
#pragma unroll
        for (int im = 0; im < 2; im++) {
            const int row = rowBase + wm + im * 16 + g;
            float v0 = acc[im][i][0] + b0;
            float v1 = acc[im][i][1] + b1;
            float v2 = acc[im][i][2] + b0;
            float v3 = acc[im][i][3] + b1;
            if (RELU) {
                v0 = fmaxf(v0, 0.f); v1 = fmaxf(v1, 0.f);
                v2 = fmaxf(v2, 0.f); v3 = fmaxf(v3, 0.f);
            }
            *(float2*)&C[(size_t)row * N + col] = make_float2(v0, v1);
            *(float2*)&C[(size_t)(row + 8) * N + col] = make_float2(v2, v3);
        }
    }
}

// ------------------------------- launcher ----------------------------------
static inline int cdiv(int a, int b) { return (a + b - 1) / b; }

extern "C" void kernel_launch(void* const* d_in, const int* in_sizes, int n_in,
                              void* d_out, int out_size) {
    const float* x   = (const float*)d_in[0];
    const float* Wl0 = (const float*)d_in[1];
    const float* bl0 = (const float*)d_in[2];
    const float* Wr0 = (const float*)d_in[3];
    const float* Wl1 = (const float*)d_in[4];
    const float* bl1 = (const float*)d_in[5];
    const float* Wr1 = (const float*)d_in[6];
    const float* Wl2 = (const float*)d_in[7];
    const float* bl2 = (const float*)d_in[8];
    const float* Wr2 = (const float*)d_in[9];
    const int* es0 = (const int*)d_in[10];
    const int* ed0 = (const int*)d_in[11];
    const int* es1 = (const int*)d_in[12];
    const int* ed1 = (const int*)d_in[13];
    const int* es2 = (const int*)d_in[14];
    const int* ed2 = (const int*)d_in[15];
    float* out = (float*)d_out;

    float *mean0, *h0, *mean1, *h1, *mean2;
    __nv_bfloat16 *wt0h, *wt0l, *wt1h, *wt1l, *wt2h, *wt2l;
    int *cnt0, *off0, *cur0, *esrc0;
    int *cnt1, *off1, *cur1, *esrc1;
    int *cnt2, *off2, *cur2, *esrc2;
    int *bsum, *bpre;
    cudaGetSymbolAddress((void**)&mean0, g_mean0);
    cudaGetSymbolAddress((void**)&h0, g_h0);
    cudaGetSymbolAddress((void**)&mean1, g_mean1);
    cudaGetSymbolAddress((void**)&h1, g_h1);
    cudaGetSymbolAddress((void**)&mean2, g_mean2);
    cudaGetSymbolAddress((void**)&wt0h, g_wt0h);
    cudaGetSymbolAddress((void**)&wt0l, g_wt0l);
    cudaGetSymbolAddress((void**)&wt1h, g_wt1h);
    cudaGetSymbolAddress((void**)&wt1l, g_wt1l);
    cudaGetSymbolAddress((void**)&wt2h, g_wt2h);
    cudaGetSymbolAddress((void**)&wt2l, g_wt2l);
    cudaGetSymbolAddress((void**)&cnt0, g_cnt0);
    cudaGetSymbolAddress((void**)&off0, g_off0);
    cudaGetSymbolAddress((void**)&cur0, g_cur0);
    cudaGetSymbolAddress((void**)&esrc0, g_esrc0);
    cudaGetSymbolAddress((void**)&cnt1, g_cnt1);
    cudaGetSymbolAddress((void**)&off1, g_off1);
    cudaGetSymbolAddress((void**)&cur1, g_cur1);
    cudaGetSymbolAddress((void**)&esrc1, g_esrc1);
    cudaGetSymbolAddress((void**)&cnt2, g_cnt2);
    cudaGetSymbolAddress((void**)&off2, g_off2);
    cudaGetSymbolAddress((void**)&cur2, g_cur2);
    cudaGetSymbolAddress((void**)&esrc2, g_esrc2);
    cudaGetSymbolAddress((void**)&bsum, g_bsum);
    cudaGetSymbolAddress((void**)&bpre, g_bpre);

    constexpr int SMEM_256 = 2 * 128 * 36 * 4 + 4 * 256 * 40 * 2;  // 118784
    constexpr int SMEM_64  = 2 * 128 * 36 * 4 + 4 * 64 * 40 * 2;   // 57344
    cudaFuncSetAttribute(sage_mma_gemm<256, true>,
                         cudaFuncAttributeMaxDynamicSharedMemorySize, SMEM_256);
    cudaFuncSetAttribute(sage_mma_gemm<256, false>,
                         cudaFuncAttributeMaxDynamicSharedMemorySize, SMEM_256);
    cudaFuncSetAttribute(sage_mma_gemm<64, true>,
                         cudaFuncAttributeMaxDynamicSharedMemorySize, SMEM_64);

    // weight transpose + split (independent of graph work)
    prep_w_kernel<<<cdiv(256 * 256, 256), 256>>>(Wl0, Wr0, D_IN, 2 * D_IN, D_H, wt0h, wt0l);
    prep_w_kernel<<<cdiv(256 * 512, 256), 256>>>(Wl1, Wr1, D_H, 2 * D_H, D_H, wt1h, wt1l);
    prep_w_kernel<<<cdiv(64 * 512, 256), 256>>>(Wl2, Wr2, D_H, 2 * D_H, D_OUT, wt2h, wt2l);

    // fused CSR build for all three layers (parallel 3-phase scan)
    zero_all_kernel<<<cdiv(NTOT, 256), 256>>>(cnt0, cnt1, cnt2);
    hist_all_kernel<<<cdiv(E0 + E1 + E2, 256), 256>>>(ed0, ed1, ed2, cnt0, cnt1, cnt2);
    scanA_kernel<<<NB, 1024>>>(cnt0, cnt1, cnt2, bsum);
    scanB_kernel<<<1, 32>>>(bsum, bpre);
    scanC_kernel<<<NB, 1024>>>(cnt0, cnt1, cnt2, bpre,
                               off0, cur0, off1, cur1, off2, cur2);
    scatter_all_kernel<<<cdiv(E0 + E1 + E2, 256), 256>>>(
        es0, ed0, cur0, esrc0, es1, ed1, cur1, esrc1, es2, ed2, cur2, esrc2);

    // ---------------- layer 0 ----------------
    aggregate_kernel<128><<<cdiv(N1 * 32, 256), 256>>>(x, off0, esrc0, mean0, N1);
    sage_mma_gemm<256, true><<<N1 / 128, 256, SMEM_256>>>(
        mean0, D_IN, x, D_IN, 2 * D_IN, wt0h, wt0l, bl0, h0);

    // ---------------- layer 1 ----------------
    aggregate_kernel<256><<<cdiv(N2 * 32, 256), 256>>>(h0, off1, esrc1, mean1, N2);
    sage_mma_gemm<256, false><<<N2 / 128, 256, SMEM_256>>>(
        mean1, D_H, h0, D_H, 2 * D_H, wt1h, wt1l, bl1, h1);

    // ---------------- layer 2 ----------------
    aggregate_kernel<256><<<cdiv(N3 * 32, 256), 256>>>(h1, off2, esrc2, mean2, N3);
    sage_mma_gemm<64, true><<<N3 / 128, 256, SMEM_64>>>(
        mean2, D_H, h1, D_H, 2 * D_H, wt2h, wt2l, bl2, out);
}

// round 7
// speedup vs baseline: 2.4156x; 1.0710x over previous
#include <cuda_runtime.h>
#include <cuda_bf16.h>
#include <cstdint>

// ---------------------------------------------------------------------------
// GNN_37082747634058: 3-layer GraphSAGE(mean) forward.
//   fused CSR build (parallel 3-phase scan) -> per layer: warp-per-dst mean ->
//   GEMM out = relu?( [mean | x_dst] @ [Wl;Wr] + bl )
// All GEMMs: mma.sync m16n8k16 bf16, 3-term split (hi*hi + hi*lo + lo*hi,
// fp32 accum). B fragments via ldmatrix.x4; 3-stage cp.async pipeline.
// ---------------------------------------------------------------------------

#define N0 1363968
#define N1 123904
#define N2 11264
#define N3 1024
#define E0 1239040
#define E1 112640
#define E2 10240
#define D_IN 128
#define D_H  256
#define D_OUT 64

#define NTOT (N1 + N2 + N3)
#define EPB 4096
#define NB  ((NTOT + EPB - 1) / EPB)

// ------------------------- static device scratch ---------------------------
__device__ float g_mean0[(size_t)N1 * D_IN];
__device__ float g_h0   [(size_t)N1 * D_H];
__device__ float g_mean1[(size_t)N2 * D_H];
__device__ float g_h1   [(size_t)N2 * D_H];
__device__ float g_mean2[(size_t)N3 * D_H];

__device__ __nv_bfloat16 g_wt0h[256 * 256], g_wt0l[256 * 256];
__device__ __nv_bfloat16 g_wt1h[256 * 512], g_wt1l[256 * 512];
__device__ __nv_bfloat16 g_wt2h[64 * 512],  g_wt2l[64 * 512];

__device__ int g_cnt0[N1], g_off0[N1 + 1], g_cur0[N1], g_esrc0[E0];
__device__ int g_cnt1[N2], g_off1[N2 + 1], g_cur1[N2], g_esrc1[E1];
__device__ int g_cnt2[N3], g_off2[N3 + 1], g_cur2[N3], g_esrc2[E2];
__device__ int g_bsum[NB + 1], g_bpre[NB + 1];

// ------------------------------ helpers ------------------------------------
__device__ __forceinline__ void mma_bf16(float (&c)[4], const uint32_t (&a)[4],
                                         const uint32_t (&b)[2]) {
    asm volatile(
        "mma.sync.aligned.m16n8k16.row.col.f32.bf16.bf16.f32 "
        "{%0,%1,%2,%3}, {%4,%5,%6,%7}, {%8,%9}, {%0,%1,%2,%3};"
        : "+f"(c[0]), "+f"(c[1]), "+f"(c[2]), "+f"(c[3])
        : "r"(a[0]), "r"(a[1]), "r"(a[2]), "r"(a[3]), "r"(b[0]), "r"(b[1]));
}

__device__ __forceinline__ void ldmatrix_x4(uint32_t& r0, uint32_t& r1,
                                            uint32_t& r2, uint32_t& r3,
                                            uint32_t addr) {
    asm volatile("ldmatrix.sync.aligned.m8n8.x4.shared.b16 {%0,%1,%2,%3}, [%4];"
                 : "=r"(r0), "=r"(r1), "=r"(r2), "=r"(r3) : "r"(addr));
}

__device__ __forceinline__ void split_bf16(float2 f, uint32_t& hi, uint32_t& lo) {
    __nv_bfloat162 h2 = __float22bfloat162_rn(f);
    hi = *reinterpret_cast<uint32_t*>(&h2);
    float2 hf = __bfloat1622float2(h2);
    __nv_bfloat162 l2 = __float22bfloat162_rn(make_float2(f.x - hf.x, f.y - hf.y));
    lo = *reinterpret_cast<uint32_t*>(&l2);
}

__device__ __forceinline__ void cp_async16(void* smem_dst, const void* gmem_src) {
    uint32_t s = (uint32_t)__cvta_generic_to_shared(smem_dst);
    asm volatile("cp.async.cg.shared.global [%0], [%1], 16;\n"
                 :: "r"(s), "l"(gmem_src));
}
__device__ __forceinline__ void cp_async_commit() {
    asm volatile("cp.async.commit_group;\n" ::: "memory");
}
template <int NWait>
__device__ __forceinline__ void cp_async_wait() {
    asm volatile("cp.async.wait_group %0;\n" :: "n"(NWait) : "memory");
}

// --------------------------- fused CSR build -------------------------------
__global__ void zero_all_kernel(int* c0, int* c1, int* c2) {
    int i = blockIdx.x * blockDim.x + threadIdx.x;
    if (i < N1) c0[i] = 0;
    else if (i < N1 + N2) c1[i - N1] = 0;
    else if (i < N1 + N2 + N3) c2[i - N1 - N2] = 0;
}

__global__ void hist_all_kernel(const int* d0, const int* d1, const int* d2,
                                int* c0, int* c1, int* c2) {
    int i = blockIdx.x * blockDim.x + threadIdx.x;
    if (i < E0) atomicAdd(&c0[d0[i]], 1);
    else if (i < E0 + E1) atomicAdd(&c1[d1[i - E0]], 1);
    else if (i < E0 + E1 + E2) atomicAdd(&c2[d2[i - E0 - E1]], 1);
}

__device__ __forceinline__ int cnt_cat(const int* c0, const int* c1, const int* c2,
                                       int i) {
    if (i < N1) return c0[i];
    if (i < N1 + N2) return c1[i - N1];
    return c2[i - N1 - N2];
}

__global__ void scanA_kernel(const int* c0, const int* c1, const int* c2,
                             int* bsum) {
    __shared__ int wsum[32];
    const int t = threadIdx.x, lane = t & 31, w = t >> 5;
    const int base = blockIdx.x * EPB + t * 4;
    int s = 0;
#pragma unroll
    for (int i = 0; i < 4; i++) {
        int idx = base + i;
        if (idx < NTOT) s += cnt_cat(c0, c1, c2, idx);
    }
#pragma unroll
    for (int d = 16; d > 0; d >>= 1) s += __shfl_down_sync(0xffffffffu, s, d);
    if (lane == 0) wsum[w] = s;
    __syncthreads();
    if (w == 0) {
        int v = wsum[lane];
#pragma unroll
        for (int d = 16; d > 0; d >>= 1) v += __shfl_down_sync(0xffffffffu, v, d);
        if (lane == 0) bsum[blockIdx.x] = v;
    }
}

__global__ void scanB_kernel(const int* bsum, int* bpre) {
    if (threadIdx.x == 0) {
        int run = 0;
        for (int b = 0; b < NB; b++) { bpre[b] = run; run += bsum[b]; }
    }
}

__global__ void scanC_kernel(const int* c0, const int* c1, const int* c2,
                             const int* bpre,
                             int* o0, int* u0, int* o1, int* u1,
                             int* o2, int* u2) {
    __shared__ int wsum[32];
    const int t = threadIdx.x, lane = t & 31, w = t >> 5;
    const int base = blockIdx.x * EPB + t * 4;
    int v[4];
#pragma unroll
    for (int i = 0; i < 4; i++) {
        int idx = base + i;
        v[i] = (idx < NTOT) ? cnt_cat(c0, c1, c2, idx) : 0;
    }
    int s = v[0] + v[1] + v[2] + v[3];
    int incl = s;
#pragma unroll
    for (int d = 1; d < 32; d <<= 1) {
        int o = __shfl_up_sync(0xffffffffu, incl, d);
        if (lane >= d) incl += o;
    }
    if (lane == 31) wsum[w] = incl;
    __syncthreads();
    if (w == 0) {
        int x = wsum[lane];
        int xi = x;
#pragma unroll
        for (int d = 1; d < 32; d <<= 1) {
            int o = __shfl_up_sync(0xffffffffu, xi, d);
            if (lane >= d) xi += o;
        }
        wsum[lane] = xi - x;
    }
    __syncthreads();
    int run = bpre[blockIdx.x] + wsum[w] + (incl - s);
#pragma unroll
    for (int i = 0; i < 4; i++) {
        int idx = base + i;
        if (idx < NTOT) {
            if (idx < N1)            { o0[idx] = run;            u0[idx] = run; }
            else if (idx < N1 + N2)  { int j = idx - N1;
                                       o1[j] = run - E0;         u1[j] = run - E0; }
            else                     { int j = idx - N1 - N2;
                                       o2[j] = run - E0 - E1;    u2[j] = run - E0 - E1; }
        }
        run += v[i];
    }
    if (blockIdx.x == 0 && t == 0) {
        o0[N1] = E0; o1[N2] = E1; o2[N3] = E2;
    }
}

__global__ void scatter_all_kernel(const int* s0, const int* d0, int* u0, int* e0,
                                   const int* s1, const int* d1, int* u1, int* e1,
                                   const int* s2, const int* d2, int* u2, int* e2) {
    int i = blockIdx.x * blockDim.x + threadIdx.x;
    if (i < E0) {
        int p = atomicAdd(&u0[d0[i]], 1); e0[p] = s0[i];
    } else if (i < E0 + E1) {
        int j = i - E0;
        int p = atomicAdd(&u1[d1[j]], 1); e1[p] = s1[j];
    } else if (i < E0 + E1 + E2) {
        int j = i - E0 - E1;
        int p = atomicAdd(&u2[d2[j]], 1); e2[p] = s2[j];
    }
}

// ------------------------- warp-per-dst mean aggregation -------------------
template <int D>
__global__ void aggregate_kernel(const float* __restrict__ X,
                                 const int* __restrict__ off,
                                 const int* __restrict__ srcs,
                                 float* __restrict__ out, int n_dst) {
    int g = (blockIdx.x * blockDim.x + threadIdx.x) >> 5;
    if (g >= n_dst) return;
    int lane = threadIdx.x & 31;
    int beg = off[g], end = off[g + 1];
    float4 a0 = make_float4(0.f, 0.f, 0.f, 0.f);
    float4 a1 = make_float4(0.f, 0.f, 0.f, 0.f);
    int j = beg;
    for (; j + 3 < end; j += 4) {
        int s0 = srcs[j], s1 = srcs[j + 1], s2 = srcs[j + 2], s3 = srcs[j + 3];
        const float4* r0 = (const float4*)(X + (size_t)s0 * D);
        const float4* r1 = (const float4*)(X + (size_t)s1 * D);
        const float4* r2 = (const float4*)(X + (size_t)s2 * D);
        const float4* r3 = (const float4*)(X + (size_t)s3 * D);
        float4 v0 = r0[lane], v1 = r1[lane], v2 = r2[lane], v3 = r3[lane];
        a0.x += (v0.x + v1.x) + (v2.x + v3.x);
        a0.y += (v0.y + v1.y) + (v2.y + v3.y);
        a0.z += (v0.z + v1.z) + (v2.z + v3.z);
        a0.w += (v0.w + v1.w) + (v2.w + v3.w);
        if (D == 256) {
            float4 u0 = r0[lane + 32], u1 = r1[lane + 32];
            float4 u2 = r2[lane + 32], u3 = r3[lane + 32];
            a1.x += (u0.x + u1.x) + (u2.x + u3.x);
            a1.y += (u0.y + u1.y) + (u2.y + u3.y);
            a1.z += (u0.z + u1.z) + (u2.z + u3.z);
            a1.w += (u0.w + u1.w) + (u2.w + u3.w);
        }
    }
    for (; j < end; j++) {
        int s = srcs[j];
        const float4* row = (const float4*)(X + (size_t)s * D);
        float4 v = row[lane];
        a0.x += v.x; a0.y += v.y; a0.z += v.z; a0.w += v.w;
        if (D == 256) {
            float4 u = row[lane + 32];
            a1.x += u.x; a1.y += u.y; a1.z += u.z; a1.w += u.w;
        }
    }
    int c = end - beg;
    float inv = 1.0f / (float)(c > 0 ? c : 1);
    float4* o = (float4*)(out + (size_t)g * D);
    o[lane] = make_float4(a0.x * inv, a0.y * inv, a0.z * inv, a0.w * inv);
    if (D == 256)
        o[lane + 32] = make_float4(a1.x * inv, a1.y * inv, a1.z * inv, a1.w * inv);
}

// ---------------- weight transpose + bf16 hi/lo split ----------------------
__global__ void prep_w_kernel(const float* __restrict__ Wl, const float* __restrict__ Wr,
                              int K1, int K, int N,
                              __nv_bfloat16* __restrict__ hi,
                              __nv_bfloat16* __restrict__ lo) {
    int idx = blockIdx.x * blockDim.x + threadIdx.x;
    if (idx >= N * K) return;
    int n = idx / K, k = idx % K;
    float v = (k < K1) ? Wl[(size_t)k * N + n] : Wr[(size_t)(k - K1) * N + n];
    __nv_bfloat16 h = __float2bfloat16_rn(v);
    hi[(size_t)n * K + k] = h;
    lo[(size_t)n * K + k] = __float2bfloat16_rn(v - __bfloat162float(h));
}

// ----------------------- bf16x3 mma.sync SAGE GEMM -------------------------
// CTA tile 128 x N, 8 warps (4m x 2n). A fp32 in smem (reg split);
// B bf16 hi/lo via cp.async, 3-stage pipeline, ldmatrix.x4 fragments.
template <int N, bool RELU>
__global__ void __launch_bounds__(256, 1)
sage_mma_gemm(const float* __restrict__ Aagg, int K1,
              const float* __restrict__ Adst, int ldDst, int K,
              const __nv_bfloat16* __restrict__ Wth,
              const __nv_bfloat16* __restrict__ Wtl,
              const float* __restrict__ bias, float* __restrict__ C) {
    extern __shared__ char smem[];
    constexpr int ASTR = 36;                    // floats per A row
    constexpr int BSTR = 40;                    // halves per B row (80 B)
    constexpr int ABYTES = 128 * ASTR * 4;      // 18432
    constexpr int BBYTES = N * BSTR * 2;        // 20480 @256
    constexpr int STAGE = ABYTES + 2 * BBYTES;  // 59392 @256
    const int tid = threadIdx.x;
    const int wid = tid >> 5;
    const int lane = tid & 31;
    const int g = lane >> 2;
    const int t = lane & 3;
    const int wm = (wid & 3) * 32;
    const int wn = (wid >> 2) * (N / 2);
    const int rowBase = blockIdx.x * 128;
    const int NC = K / 32;
    constexpr int NIN = N / 16;                 // 8-col tiles per warp

    // ldmatrix per-lane row offset within the warp's B panel:
    // quad q: q&2 selects +8 n-rows, q&1 selects +8 k-cols.
    const int q = lane >> 3;
    const uint32_t bLaneOff =
        (uint32_t)((wn + ((q & 2) << 2) + (lane & 7)) * (BSTR * 2) + (q & 1) * 16);

    float acc[2][NIN][4];
#pragma unroll
    for (int im = 0; im < 2; im++)
#pragma unroll
        for (int i = 0; i < NIN; i++)
#pragma unroll
            for (int qq = 0; qq < 4; qq++) acc[im][i][qq] = 0.f;

    auto issue_chunk = [&](int kc, int b) {
        char* stage = smem + b * STAGE;
        float* As = (float*)stage;
        __nv_bfloat16* Bh = (__nv_bfloat16*)(stage + ABYTES);
        __nv_bfloat16* Bl = (__nv_bfloat16*)(stage + ABYTES + BBYTES);
        const int acol = kc * 32;
        const bool inAgg = acol < K1;
        const float* abase = inAgg ? (Aagg + acol) : (Adst + (acol - K1));
        const int ald = inAgg ? K1 : ldDst;
#pragma unroll
        for (int p = 0; p < 4; p++) {
            int idx = p * 256 + tid;
            int r = idx >> 3, c4 = idx & 7;
            cp_async16(&As[r * ASTR + c4 * 4],
                       abase + (size_t)(rowBase + r) * ald + c4 * 4);
        }
#pragma unroll
        for (int p = 0; p < N / 64; p++) {
            int idx = p * 256 + tid;
            int r = idx >> 2, c8 = idx & 3;
            cp_async16(&Bh[r * BSTR + c8 * 8], Wth + (size_t)r * K + acol + c8 * 8);
            cp_async16(&Bl[r * BSTR + c8 * 8], Wtl + (size_t)r * K + acol + c8 * 8);
        }
        cp_async_commit();
    };

    issue_chunk(0, 0);
    if (NC > 1) issue_chunk(1, 1);

    for (int kc = 0; kc < NC; kc++) {
        const int b = kc % 3;
        __syncthreads();   // prior compute done -> safe to overwrite buffer
        if (kc + 2 < NC) {
            issue_chunk(kc + 2, (kc + 2) % 3);
            cp_async_wait<2>();
        } else if (kc + 1 < NC) {
            cp_async_wait<1>();
        } else {
            cp_async_wait<0>();
        }
        __syncthreads();   // chunk kc visible to all warps

        char* stage = smem + b * STAGE;
        const float* Ab = (const float*)stage;
        const uint32_t bhAddr =
            (uint32_t)__cvta_generic_to_shared(stage + ABYTES) + bLaneOff;
        const uint32_t blAddr = bhAddr + BBYTES;
#pragma unroll
        for (int s = 0; s < 2; s++) {
            const int kb = s * 16;
            uint32_t ah[2][4], al[2][4];
#pragma unroll
            for (int im = 0; im < 2; im++) {
                const int r0 = wm + im * 16 + g;
                float2 f0 = *(const float2*)&Ab[r0 * ASTR + kb + 2 * t];
                float2 f1 = *(const float2*)&Ab[(r0 + 8) * ASTR + kb + 2 * t];
                float2 f2 = *(const float2*)&Ab[r0 * ASTR + kb + 8 + 2 * t];
                float2 f3 = *(const float2*)&Ab[(r0 + 8) * ASTR + kb + 8 + 2 * t];
                split_bf16(f0, ah[im][0], al[im][0]);
                split_bf16(f1, ah[im][1], al[im][1]);
                split_bf16(f2, ah[im][2], al[im][2]);
                split_bf16(f3, ah[im][3], al[im][3]);
            }
#pragma unroll
            for (int i2 = 0; i2 < NIN / 2; i2++) {
                const uint32_t off = (uint32_t)(i2 * 16 * (BSTR * 2) + kb * 2);
                uint32_t bh[4], bl[4];
                ldmatrix_x4(bh[0], bh[1], bh[2], bh[3], bhAddr + off);
                ldmatrix_x4(bl[0], bl[1], bl[2], bl[3], blAddr + off);
                const uint32_t h0[2] = {bh[0], bh[1]};
                const uint32_t h1[2] = {bh[2], bh[3]};
                const uint32_t l0[2] = {bl[0], bl[1]};
                const uint32_t l1[2] = {bl[2], bl[3]};
                mma_bf16(acc[0][2 * i2], ah[0], h0);
                mma_bf16(acc[1][2 * i2], ah[1], h0);
                mma_bf16(acc[0][2 * i2], ah[0], l0);
                mma_bf16(acc[1][2 * i2], ah[1], l0);
                mma_bf16(acc[0][2 * i2], al[0], h0);
                mma_bf16(acc[1][2 * i2], al[1], h0);
                mma_bf16(acc[0][2 * i2 + 1], ah[0], h1);
                mma_bf16(acc[1][2 * i2 + 1], ah[1], h1);
                mma_bf16(acc[0][2 * i2 + 1], ah[0], l1);
                mma_bf16(acc[1][2 * i2 + 1], ah[1], l1);
                mma_bf16(acc[0][2 * i2 + 1], al[0], h1);
                mma_bf16(acc[1][2 * i2 + 1], al[1], h1);
            }
        }
    }

    // ---- epilogue ----
#pragma unroll
    for (int i = 0; i < NIN; i++) {
        const int col = wn + i * 8 + 2 * t;
        const float b0 = __ldg(bias + col);
        const float b1 = __ldg(bias + col + 1);
#pragma unroll
        for (int im = 0; im < 2; im++) {
            const int row = rowBase + wm + im * 16 + g;
            float v0 = acc[im][i][0] + b0;
            float v1 = acc[im][i][1] + b1;
            float v2 = acc[im][i][2] + b0;
            float v3 = acc[im][i][3] + b1;
            if (RELU) {
                v0 = fmaxf(v0, 0.f); v1 = fmaxf(v1, 0.f);
                v2 = fmaxf(v2, 0.f); v3 = fmaxf(v3, 0.f);
            }
            *(float2*)&C[(size_t)row * N + col] = make_float2(v0, v1);
            *(float2*)&C[(size_t)(row + 8) * N + col] = make_float2(v2, v3);
        }
    }
}

// ------------------------------- launcher ----------------------------------
static inline int cdiv(int a, int b) { return (a + b - 1) / b; }

extern "C" void kernel_launch(void* const* d_in, const int* in_sizes, int n_in,
                              void* d_out, int out_size) {
    const float* x   = (const float*)d_in[0];
    const float* Wl0 = (const float*)d_in[1];
    const float* bl0 = (const float*)d_in[2];
    const float* Wr0 = (const float*)d_in[3];
    const float* Wl1 = (const float*)d_in[4];
    const float* bl1 = (const float*)d_in[5];
    const float* Wr1 = (const float*)d_in[6];
    const float* Wl2 = (const float*)d_in[7];
    const float* bl2 = (const float*)d_in[8];
    const float* Wr2 = (const float*)d_in[9];
    const int* es0 = (const int*)d_in[10];
    const int* ed0 = (const int*)d_in[11];
    const int* es1 = (const int*)d_in[12];
    const int* ed1 = (const int*)d_in[13];
    const int* es2 = (const int*)d_in[14];
    const int* ed2 = (const int*)d_in[15];
    float* out = (float*)d_out;

    float *mean0, *h0, *mean1, *h1, *mean2;
    __nv_bfloat16 *wt0h, *wt0l, *wt1h, *wt1l, *wt2h, *wt2l;
    int *cnt0, *off0, *cur0, *esrc0;
    int *cnt1, *off1, *cur1, *esrc1;
    int *cnt2, *off2, *cur2, *esrc2;
    int *bsum, *bpre;
    cudaGetSymbolAddress((void**)&mean0, g_mean0);
    cudaGetSymbolAddress((void**)&h0, g_h0);
    cudaGetSymbolAddress((void**)&mean1, g_mean1);
    cudaGetSymbolAddress((void**)&h1, g_h1);
    cudaGetSymbolAddress((void**)&mean2, g_mean2);
    cudaGetSymbolAddress((void**)&wt0h, g_wt0h);
    cudaGetSymbolAddress((void**)&wt0l, g_wt0l);
    cudaGetSymbolAddress((void**)&wt1h, g_wt1h);
    cudaGetSymbolAddress((void**)&wt1l, g_wt1l);
    cudaGetSymbolAddress((void**)&wt2h, g_wt2h);
    cudaGetSymbolAddress((void**)&wt2l, g_wt2l);
    cudaGetSymbolAddress((void**)&cnt0, g_cnt0);
    cudaGetSymbolAddress((void**)&off0, g_off0);
    cudaGetSymbolAddress((void**)&cur0, g_cur0);
    cudaGetSymbolAddress((void**)&esrc0, g_esrc0);
    cudaGetSymbolAddress((void**)&cnt1, g_cnt1);
    cudaGetSymbolAddress((void**)&off1, g_off1);
    cudaGetSymbolAddress((void**)&cur1, g_cur1);
    cudaGetSymbolAddress((void**)&esrc1, g_esrc1);
    cudaGetSymbolAddress((void**)&cnt2, g_cnt2);
    cudaGetSymbolAddress((void**)&off2, g_off2);
    cudaGetSymbolAddress((void**)&cur2, g_cur2);
    cudaGetSymbolAddress((void**)&esrc2, g_esrc2);
    cudaGetSymbolAddress((void**)&bsum, g_bsum);
    cudaGetSymbolAddress((void**)&bpre, g_bpre);

    constexpr int SMEM_256 = 3 * (128 * 36 * 4 + 2 * 256 * 40 * 2);  // 178176
    constexpr int SMEM_64  = 3 * (128 * 36 * 4 + 2 * 64 * 40 * 2);   // 86016
    cudaFuncSetAttribute(sage_mma_gemm<256, true>,
                         cudaFuncAttributeMaxDynamicSharedMemorySize, SMEM_256);
    cudaFuncSetAttribute(sage_mma_gemm<256, false>,
                         cudaFuncAttributeMaxDynamicSharedMemorySize, SMEM_256);
    cudaFuncSetAttribute(sage_mma_gemm<64, true>,
                         cudaFuncAttributeMaxDynamicSharedMemorySize, SMEM_64);

    // weight transpose + split (independent of graph work)
    prep_w_kernel<<<cdiv(256 * 256, 256), 256>>>(Wl0, Wr0, D_IN, 2 * D_IN, D_H, wt0h, wt0l);
    prep_w_kernel<<<cdiv(256 * 512, 256), 256>>>(Wl1, Wr1, D_H, 2 * D_H, D_H, wt1h, wt1l);
    prep_w_kernel<<<cdiv(64 * 512, 256), 256>>>(Wl2, Wr2, D_H, 2 * D_H, D_OUT, wt2h, wt2l);

    // fused CSR build (parallel 3-phase scan)
    zero_all_kernel<<<cdiv(NTOT, 256), 256>>>(cnt0, cnt1, cnt2);
    hist_all_kernel<<<cdiv(E0 + E1 + E2, 256), 256>>>(ed0, ed1, ed2, cnt0, cnt1, cnt2);
    scanA_kernel<<<NB, 1024>>>(cnt0, cnt1, cnt2, bsum);
    scanB_kernel<<<1, 32>>>(bsum, bpre);
    scanC_kernel<<<NB, 1024>>>(cnt0, cnt1, cnt2, bpre,
                               off0, cur0, off1, cur1, off2, cur2);
    scatter_all_kernel<<<cdiv(E0 + E1 + E2, 256), 256>>>(
        es0, ed0, cur0, esrc0, es1, ed1, cur1, esrc1, es2, ed2, cur2, esrc2);

    // ---------------- layer 0 ----------------
    aggregate_kernel<128><<<cdiv(N1 * 32, 256), 256>>>(x, off0, esrc0, mean0, N1);
    sage_mma_gemm<256, true><<<N1 / 128, 256, SMEM_256>>>(
        mean0, D_IN, x, D_IN, 2 * D_IN, wt0h, wt0l, bl0, h0);

    // ---------------- layer 1 ----------------
    aggregate_kernel<256><<<cdiv(N2 * 32, 256), 256>>>(h0, off1, esrc1, mean1, N2);
    sage_mma_gemm<256, false><<<N2 / 128, 256, SMEM_256>>>(
        mean1, D_H, h0, D_H, 2 * D_H, wt1h, wt1l, bl1, h1);

    // ---------------- layer 2 ----------------
    aggregate_kernel<256><<<cdiv(N3 * 32, 256), 256>>>(h1, off2, esrc2, mean2, N3);
    sage_mma_gemm<64, true><<<N3 / 128, 256, SMEM_64>>>(
        mean2, D_H, h1, D_H, 2 * D_H, wt2h, wt2l, bl2, out);
}